// round 2
// baseline (speedup 1.0000x reference)
#include <cuda_runtime.h>
#include <math.h>

// ---------------------------------------------------------------------------
// Problem constants
// ---------------------------------------------------------------------------
#define BB     4
#define TT     8
#define RESO   32
#define CC     128
#define LL     (TT * RESO * RESO)     // 8192
#define MROWS  (BB * LL)              // 32768
#define HID    (4 * CC)               // 512

// ---------------------------------------------------------------------------
// Device scratch (static allocation only, per harness rules)
// ---------------------------------------------------------------------------
__device__ float g_img[(size_t)MROWS * CC];       // LN1 output
__device__ float g_qkv[(size_t)MROWS * 3 * CC];   // qkv
__device__ float g_att[(size_t)MROWS * CC];       // attention output (concat branches)
__device__ float g_x2 [(size_t)MROWS * CC];       // x + proj(att)
__device__ float g_y  [(size_t)MROWS * CC];       // LN2 output
__device__ float g_hid[(size_t)MROWS * HID];      // gelu(fc1)

// ---------------------------------------------------------------------------
// LayerNorm: one warp per token (C = 128 -> 4 floats / lane)
// ---------------------------------------------------------------------------
__global__ void ln_kernel(const float* __restrict__ x,
                          const float* __restrict__ w,
                          const float* __restrict__ b,
                          float* __restrict__ out)
{
    int row  = blockIdx.x * 8 + threadIdx.y;
    int lane = threadIdx.x;
    const float4* rp = (const float4*)(x + (size_t)row * CC);
    float4 v = rp[lane];
    float s  = v.x + v.y + v.z + v.w;
    float ss = v.x * v.x + v.y * v.y + v.z * v.z + v.w * v.w;
    #pragma unroll
    for (int o = 16; o > 0; o >>= 1) {
        s  += __shfl_xor_sync(0xffffffffu, s,  o);
        ss += __shfl_xor_sync(0xffffffffu, ss, o);
    }
    float mean = s * (1.0f / CC);
    float var  = ss * (1.0f / CC) - mean * mean;
    float rstd = rsqrtf(var + 1e-5f);
    float4 wv = ((const float4*)w)[lane];
    float4 bv = ((const float4*)b)[lane];
    float4 r;
    r.x = (v.x - mean) * rstd * wv.x + bv.x;
    r.y = (v.y - mean) * rstd * wv.y + bv.y;
    r.z = (v.z - mean) * rstd * wv.z + bv.z;
    r.w = (v.w - mean) * rstd * wv.w + bv.w;
    ((float4*)(out + (size_t)row * CC))[lane] = r;
}

// ---------------------------------------------------------------------------
// Tiled SGEMM:  C[M,N] = A[M,K] @ B[N,K]^T  (+ epilogue)
// EPI: 0 none, 1 bias, 2 bias+gelu(exact), 3 bias+residual
// Block tile 128x128, K-step 8, 256 threads, 8x8 per-thread micro tile.
// ---------------------------------------------------------------------------
__device__ __forceinline__ float gelu_exact(float v)
{
    return 0.5f * v * (1.0f + erff(v * 0.70710678118654752f));
}

template <int EPI>
__global__ void __launch_bounds__(256)
sgemm_kernel(int Nd, int Kd,
             const float* __restrict__ A,
             const float* __restrict__ Bm,
             const float* __restrict__ bias,
             const float* __restrict__ resid,
             float* __restrict__ Cout)
{
    __shared__ float As[8][132];
    __shared__ float Bs[8][132];

    int tid = threadIdx.x;
    int tx  = tid & 15;          // 0..15 -> N direction
    int ty  = tid >> 4;          // 0..15 -> M direction
    int m0  = blockIdx.y * 128;
    int n0  = blockIdx.x * 128;

    int lr = tid >> 1;           // 0..127 row within tile
    int lk = (tid & 1) * 4;      // 0 or 4

    const float* Aptr = A  + (size_t)(m0 + lr) * Kd + lk;
    const float* Bptr = Bm + (size_t)(n0 + lr) * Kd + lk;

    float acc[8][8];
    #pragma unroll
    for (int i = 0; i < 8; i++)
        #pragma unroll
        for (int j = 0; j < 8; j++) acc[i][j] = 0.0f;

    for (int kt = 0; kt < Kd; kt += 8) {
        float4 a4 = *(const float4*)(Aptr + kt);
        float4 b4 = *(const float4*)(Bptr + kt);
        As[lk + 0][lr] = a4.x; As[lk + 1][lr] = a4.y;
        As[lk + 2][lr] = a4.z; As[lk + 3][lr] = a4.w;
        Bs[lk + 0][lr] = b4.x; Bs[lk + 1][lr] = b4.y;
        Bs[lk + 2][lr] = b4.z; Bs[lk + 3][lr] = b4.w;
        __syncthreads();
        #pragma unroll
        for (int k = 0; k < 8; k++) {
            float ar[8], br[8];
            #pragma unroll
            for (int i = 0; i < 8; i++) ar[i] = As[k][ty * 8 + i];
            #pragma unroll
            for (int j = 0; j < 8; j++) br[j] = Bs[k][tx * 8 + j];
            #pragma unroll
            for (int i = 0; i < 8; i++)
                #pragma unroll
                for (int j = 0; j < 8; j++)
                    acc[i][j] += ar[i] * br[j];
        }
        __syncthreads();
    }

    #pragma unroll
    for (int i = 0; i < 8; i++) {
        int m = m0 + ty * 8 + i;
        size_t off = (size_t)m * Nd + n0 + tx * 8;
        #pragma unroll
        for (int j = 0; j < 8; j++) {
            float v = acc[i][j];
            if (EPI >= 1) v += bias[n0 + tx * 8 + j];
            if (EPI == 2) v = gelu_exact(v);
            if (EPI == 3) v += resid[off + j];
            Cout[off + j] = v;
        }
    }
}

// ---------------------------------------------------------------------------
// Windowed attention + fused LePE (depthwise 3x3x3 conv on v inside window)
// One CTA per (branch, window, head): 512 queries x 512 keys x hd=16.
// 256 threads; each thread owns 2 query rows. k/v tiles in dynamic smem,
// padded to stride 17 so the conv gathers are bank-conflict-free.
// Softmax without running max: scores here are tiny (sigma~0.05); clamp at 30
// keeps exp finite in any case.
// ---------------------------------------------------------------------------
#define ATT_SMEM_FLOATS (2 * 512 * 17 + 16 * 27 + 16)

__global__ void __launch_bounds__(256, 1)
attn_kernel(const float* __restrict__ qkv,
            const float* __restrict__ conv_w0, const float* __restrict__ conv_b0,
            const float* __restrict__ conv_w1, const float* __restrict__ conv_b1)
{
    extern __shared__ float smem[];
    float* ks = smem;                    // [512][17]
    float* vs = smem + 512 * 17;         // [512][17]
    float* cw = vs + 512 * 17;           // [16][27]
    float* cb = cw + 16 * 27;            // [16]

    int cta    = blockIdx.x;
    int branch = cta >> 8;               // 0 or 1
    int rem    = cta & 255;
    int win    = rem >> 2;               // 0..63
    int head   = rem & 3;

    int Hsp   = branch ? 4 : 32;
    int Wsp   = branch ? 32 : 4;
    int lw    = branch ? 5 : 2;          // log2(Wsp)
    int wmask = Wsp - 1;
    int nWh   = branch ? 8 : 1;          // 32 / Hsp
    int nWw   = branch ? 1 : 8;          // 32 / Wsp
    int nwin  = nWh * nWw;               // 8

    int bidx = win >> 4;
    int wrem = win & 15;
    int wt = wrem / nwin;
    int wsp = wrem % nwin;
    int wh = wsp / nWw;
    int ww = wsp % nWw;

    int choff = branch * 64 + head * 16; // channel offset in the 128-wide concat
    int tid = threadIdx.x;

    // token index for in-window position p
    // p = (it*Hsp + ih)*Wsp + iw,  Hsp*Wsp == 128 always
    #define WIN_L(p, itv, ihv, iwv)                                     \
        int itv = (p) >> 7;                                             \
        int _r  = (p) & 127;                                            \
        int ihv = _r >> lw;                                             \
        int iwv = _r & wmask;                                           \
        int _t  = wt * 4 + itv;                                         \
        int _h  = wh * Hsp + ihv;                                       \
        int _w  = ww * Wsp + iwv;                                       \
        int lrow = bidx * LL + (_t << 10) + (_h << 5) + _w;

    // ---- load k / v tiles into smem ----
    for (int p = tid; p < 512; p += 256) {
        WIN_L(p, it_, ih_, iw_);
        (void)it_; (void)ih_; (void)iw_;
        const float* kp = qkv + (size_t)lrow * 384 + 128 + choff;
        const float* vp = qkv + (size_t)lrow * 384 + 256 + choff;
        float4 k0 = ((const float4*)kp)[0], k1 = ((const float4*)kp)[1];
        float4 k2 = ((const float4*)kp)[2], k3 = ((const float4*)kp)[3];
        float4 v0 = ((const float4*)vp)[0], v1 = ((const float4*)vp)[1];
        float4 v2 = ((const float4*)vp)[2], v3 = ((const float4*)vp)[3];
        float* kd = ks + p * 17;
        float* vd = vs + p * 17;
        kd[0]=k0.x; kd[1]=k0.y; kd[2]=k0.z; kd[3]=k0.w;
        kd[4]=k1.x; kd[5]=k1.y; kd[6]=k1.z; kd[7]=k1.w;
        kd[8]=k2.x; kd[9]=k2.y; kd[10]=k2.z; kd[11]=k2.w;
        kd[12]=k3.x; kd[13]=k3.y; kd[14]=k3.z; kd[15]=k3.w;
        vd[0]=v0.x; vd[1]=v0.y; vd[2]=v0.z; vd[3]=v0.w;
        vd[4]=v1.x; vd[5]=v1.y; vd[6]=v1.z; vd[7]=v1.w;
        vd[8]=v2.x; vd[9]=v2.y; vd[10]=v2.z; vd[11]=v2.w;
        vd[12]=v3.x; vd[13]=v3.y; vd[14]=v3.z; vd[15]=v3.w;
    }
    const float* cwp = branch ? conv_w1 : conv_w0;
    const float* cbp = branch ? conv_b1 : conv_b0;
    for (int i = tid; i < 16 * 27; i += 256) cw[i] = cwp[head * 16 * 27 + i];
    if (tid < 16) cb[tid] = cbp[head * 16 + tid];

    // ---- load this thread's two query rows (scaled) ----
    int p0 = tid, p1 = tid + 256;
    float q0[16], q1[16];
    int row0, row1;
    {
        WIN_L(p0, a, b_, c); (void)a; (void)b_; (void)c;
        row0 = lrow;
        const float4* qp = (const float4*)(qkv + (size_t)lrow * 384 + choff);
        float4 t0 = qp[0], t1 = qp[1], t2 = qp[2], t3 = qp[3];
        q0[0]=t0.x*0.25f; q0[1]=t0.y*0.25f; q0[2]=t0.z*0.25f; q0[3]=t0.w*0.25f;
        q0[4]=t1.x*0.25f; q0[5]=t1.y*0.25f; q0[6]=t1.z*0.25f; q0[7]=t1.w*0.25f;
        q0[8]=t2.x*0.25f; q0[9]=t2.y*0.25f; q0[10]=t2.z*0.25f; q0[11]=t2.w*0.25f;
        q0[12]=t3.x*0.25f; q0[13]=t3.y*0.25f; q0[14]=t3.z*0.25f; q0[15]=t3.w*0.25f;
    }
    {
        WIN_L(p1, a, b_, c); (void)a; (void)b_; (void)c;
        row1 = lrow;
        const float4* qp = (const float4*)(qkv + (size_t)lrow * 384 + choff);
        float4 t0 = qp[0], t1 = qp[1], t2 = qp[2], t3 = qp[3];
        q1[0]=t0.x*0.25f; q1[1]=t0.y*0.25f; q1[2]=t0.z*0.25f; q1[3]=t0.w*0.25f;
        q1[4]=t1.x*0.25f; q1[5]=t1.y*0.25f; q1[6]=t1.z*0.25f; q1[7]=t1.w*0.25f;
        q1[8]=t2.x*0.25f; q1[9]=t2.y*0.25f; q1[10]=t2.z*0.25f; q1[11]=t2.w*0.25f;
        q1[12]=t3.x*0.25f; q1[13]=t3.y*0.25f; q1[14]=t3.z*0.25f; q1[15]=t3.w*0.25f;
    }
    __syncthreads();

    // ---- streaming softmax-attention (no running max; scores are tiny) ----
    float acc0[16], acc1[16];
    #pragma unroll
    for (int d = 0; d < 16; d++) { acc0[d] = 0.0f; acc1[d] = 0.0f; }
    float sum0 = 0.0f, sum1 = 0.0f;

    for (int j = 0; j < 512; j++) {
        const float* kj = ks + j * 17;
        float s0 = 0.0f, s1 = 0.0f;
        #pragma unroll
        for (int d = 0; d < 16; d++) {
            float kk = kj[d];
            s0 += q0[d] * kk;
            s1 += q1[d] * kk;
        }
        float e0 = __expf(fminf(s0, 30.0f));
        float e1 = __expf(fminf(s1, 30.0f));
        sum0 += e0; sum1 += e1;
        const float* vj = vs + j * 17;
        #pragma unroll
        for (int d = 0; d < 16; d++) {
            float vv = vj[d];
            acc0[d] += e0 * vv;
            acc1[d] += e1 * vv;
        }
    }

    float inv0 = 1.0f / sum0;
    float inv1 = 1.0f / sum1;
    float o0[16], o1[16];
    #pragma unroll
    for (int d = 0; d < 16; d++) {
        o0[d] = acc0[d] * inv0 + cb[d];
        o1[d] = acc1[d] * inv1 + cb[d];
    }

    // ---- fused LePE: depthwise 3x3x3 conv over the window (zero pad) ----
    {
        int it0 = p0 >> 7; int r0_ = p0 & 127; int ih0 = r0_ >> lw; int iw0 = r0_ & wmask;
        int it1 = p1 >> 7; int r1_ = p1 & 127; int ih1 = r1_ >> lw; int iw1 = r1_ & wmask;
        #pragma unroll
        for (int dz = 0; dz < 3; dz++) {
            #pragma unroll
            for (int dy = 0; dy < 3; dy++) {
                #pragma unroll
                for (int dx = 0; dx < 3; dx++) {
                    int widx = dz * 9 + dy * 3 + dx;
                    // position 0
                    {
                        int z = it0 + dz - 1, y = ih0 + dy - 1, x = iw0 + dx - 1;
                        if (z >= 0 && z < 4 && y >= 0 && y < Hsp && x >= 0 && x < Wsp) {
                            const float* vsrc = vs + (((z << 7) + (y << lw) + x) * 17);
                            #pragma unroll
                            for (int d = 0; d < 16; d++)
                                o0[d] += cw[d * 27 + widx] * vsrc[d];
                        }
                    }
                    // position 1
                    {
                        int z = it1 + dz - 1, y = ih1 + dy - 1, x = iw1 + dx - 1;
                        if (z >= 0 && z < 4 && y >= 0 && y < Hsp && x >= 0 && x < Wsp) {
                            const float* vsrc = vs + (((z << 7) + (y << lw) + x) * 17);
                            #pragma unroll
                            for (int d = 0; d < 16; d++)
                                o1[d] += cw[d * 27 + widx] * vsrc[d];
                        }
                    }
                }
            }
        }
    }

    // ---- scatter to token order, concat channel layout ----
    {
        float4* op = (float4*)(g_att + (size_t)row0 * CC + choff);
        op[0] = make_float4(o0[0], o0[1], o0[2], o0[3]);
        op[1] = make_float4(o0[4], o0[5], o0[6], o0[7]);
        op[2] = make_float4(o0[8], o0[9], o0[10], o0[11]);
        op[3] = make_float4(o0[12], o0[13], o0[14], o0[15]);
    }
    {
        float4* op = (float4*)(g_att + (size_t)row1 * CC + choff);
        op[0] = make_float4(o1[0], o1[1], o1[2], o1[3]);
        op[1] = make_float4(o1[4], o1[5], o1[6], o1[7]);
        op[2] = make_float4(o1[8], o1[9], o1[10], o1[11]);
        op[3] = make_float4(o1[12], o1[13], o1[14], o1[15]);
    }
    #undef WIN_L
}

// ---------------------------------------------------------------------------
// Launch
// ---------------------------------------------------------------------------
extern "C" void kernel_launch(void* const* d_in, const int* in_sizes, int n_in,
                              void* d_out, int out_size)
{
    const float* x       = (const float*)d_in[0];
    const float* norm1_w = (const float*)d_in[1];
    const float* norm1_b = (const float*)d_in[2];
    const float* qkv_w   = (const float*)d_in[3];
    const float* conv_w0 = (const float*)d_in[4];
    const float* conv_b0 = (const float*)d_in[5];
    const float* conv_w1 = (const float*)d_in[6];
    const float* conv_b1 = (const float*)d_in[7];
    const float* proj_w  = (const float*)d_in[8];
    const float* proj_b  = (const float*)d_in[9];
    const float* norm2_w = (const float*)d_in[10];
    const float* norm2_b = (const float*)d_in[11];
    const float* fc1_w   = (const float*)d_in[12];
    const float* fc1_b   = (const float*)d_in[13];
    const float* fc2_w   = (const float*)d_in[14];
    const float* fc2_b   = (const float*)d_in[15];
    float* out = (float*)d_out;

    float *p_img, *p_qkv, *p_att, *p_x2, *p_y, *p_hid;
    cudaGetSymbolAddress((void**)&p_img, g_img);
    cudaGetSymbolAddress((void**)&p_qkv, g_qkv);
    cudaGetSymbolAddress((void**)&p_att, g_att);
    cudaGetSymbolAddress((void**)&p_x2,  g_x2);
    cudaGetSymbolAddress((void**)&p_y,   g_y);
    cudaGetSymbolAddress((void**)&p_hid, g_hid);

    int att_smem = ATT_SMEM_FLOATS * (int)sizeof(float);  // ~71.4 KB
    cudaFuncSetAttribute(attn_kernel,
                         cudaFuncAttributeMaxDynamicSharedMemorySize, att_smem);

    dim3 lnBlock(32, 8);

    // 1. LN1
    ln_kernel<<<MROWS / 8, lnBlock>>>(x, norm1_w, norm1_b, p_img);

    // 2. QKV GEMM  (32768 x 384 x 128)
    sgemm_kernel<0><<<dim3(384 / 128, MROWS / 128), 256>>>(
        384, 128, p_img, qkv_w, nullptr, nullptr, p_qkv);

    // 3. Attention + LePE (512 CTAs: 2 branches x 64 windows x 4 heads)
    attn_kernel<<<512, 256, att_smem>>>(p_qkv, conv_w0, conv_b0, conv_w1, conv_b1);

    // 4. proj + bias + residual(x) -> x2   (32768 x 128 x 128)
    sgemm_kernel<3><<<dim3(1, MROWS / 128), 256>>>(
        128, 128, p_att, proj_w, proj_b, x, p_x2);

    // 5. LN2
    ln_kernel<<<MROWS / 8, lnBlock>>>(p_x2, norm2_w, norm2_b, p_y);

    // 6. fc1 + bias + gelu  (32768 x 512 x 128)
    sgemm_kernel<2><<<dim3(512 / 128, MROWS / 128), 256>>>(
        512, 128, p_y, fc1_w, fc1_b, nullptr, p_hid);

    // 7. fc2 + bias + residual(x2) -> out  (32768 x 128 x 512)
    sgemm_kernel<3><<<dim3(1, MROWS / 128), 256>>>(
        128, 512, p_hid, fc2_w, fc2_b, p_x2, out);
}

// round 8
// speedup vs baseline: 2.9657x; 2.9657x over previous
#include <cuda_runtime.h>
#include <cuda_bf16.h>
#include <math.h>

// ---------------------------------------------------------------------------
// Problem constants
// ---------------------------------------------------------------------------
#define BB     4
#define TT     8
#define RESO   32
#define CC     128
#define LL     (TT * RESO * RESO)     // 8192
#define MROWS  (BB * LL)              // 32768
#define HID    (4 * CC)               // 512

// ---------------------------------------------------------------------------
// Device scratch (static allocation only, per harness rules)
// ---------------------------------------------------------------------------
__device__ __nv_bfloat16 g_img[(size_t)MROWS * CC];       // LN1 output (bf16)
__device__ float         g_qkv[(size_t)MROWS * 3 * CC];   // qkv (fp32 for attention accuracy)
__device__ __nv_bfloat16 g_att[(size_t)MROWS * CC];       // attention output (bf16)
__device__ float         g_x2 [(size_t)MROWS * CC];       // x + proj(att)  (fp32)
__device__ __nv_bfloat16 g_y  [(size_t)MROWS * CC];       // LN2 output (bf16)
__device__ __nv_bfloat16 g_hid[(size_t)MROWS * HID];      // gelu(fc1) (bf16)

__device__ __nv_bfloat16 g_wqkv[384 * 128];
__device__ __nv_bfloat16 g_wproj[128 * 128];
__device__ __nv_bfloat16 g_wfc1[512 * 128];
__device__ __nv_bfloat16 g_wfc2[128 * 512];

// bit-cast helper (toolkit lacks __bfloat162_as_uint)
__device__ __forceinline__ unsigned __bf2u(__nv_bfloat162 v)
{
    return *(unsigned*)&v;
}

// ---------------------------------------------------------------------------
// Weight fp32 -> bf16 conversion (one fused kernel)
// ranges: qkv [0,49152), proj [49152,65536), fc1 [65536,131072), fc2 [131072,196608)
// ---------------------------------------------------------------------------
__global__ void convert_weights(const float* __restrict__ qkvw,
                                const float* __restrict__ projw,
                                const float* __restrict__ fc1w,
                                const float* __restrict__ fc2w)
{
    int i = blockIdx.x * 256 + threadIdx.x;
    if (i < 49152)       g_wqkv[i]           = __float2bfloat16(qkvw[i]);
    else if (i < 65536)  g_wproj[i - 49152]  = __float2bfloat16(projw[i - 49152]);
    else if (i < 131072) g_wfc1[i - 65536]   = __float2bfloat16(fc1w[i - 65536]);
    else if (i < 196608) g_wfc2[i - 131072]  = __float2bfloat16(fc2w[i - 131072]);
}

// ---------------------------------------------------------------------------
// LayerNorm: one warp per token (C = 128 -> 4 floats / lane), bf16 output
// ---------------------------------------------------------------------------
__global__ void ln_kernel(const float* __restrict__ x,
                          const float* __restrict__ w,
                          const float* __restrict__ b,
                          __nv_bfloat16* __restrict__ out)
{
    int row  = blockIdx.x * 8 + threadIdx.y;
    int lane = threadIdx.x;
    const float4* rp = (const float4*)(x + (size_t)row * CC);
    float4 v = rp[lane];
    float s  = v.x + v.y + v.z + v.w;
    float ss = v.x * v.x + v.y * v.y + v.z * v.z + v.w * v.w;
    #pragma unroll
    for (int o = 16; o > 0; o >>= 1) {
        s  += __shfl_xor_sync(0xffffffffu, s,  o);
        ss += __shfl_xor_sync(0xffffffffu, ss, o);
    }
    float mean = s * (1.0f / CC);
    float var  = ss * (1.0f / CC) - mean * mean;
    float rstd = rsqrtf(var + 1e-5f);
    float4 wv = ((const float4*)w)[lane];
    float4 bv = ((const float4*)b)[lane];
    float4 r;
    r.x = (v.x - mean) * rstd * wv.x + bv.x;
    r.y = (v.y - mean) * rstd * wv.y + bv.y;
    r.z = (v.z - mean) * rstd * wv.z + bv.z;
    r.w = (v.w - mean) * rstd * wv.w + bv.w;
    uint2 u;
    u.x = __bf2u(__float22bfloat162_rn(make_float2(r.x, r.y)));
    u.y = __bf2u(__float22bfloat162_rn(make_float2(r.z, r.w)));
    ((uint2*)(out + (size_t)row * CC))[lane] = u;
}

// ---------------------------------------------------------------------------
// bf16 tensor-core GEMM:  C[M,N] = A[M,K] @ B[N,K]^T  (+ epilogue)
// EPI: 0 plain fp32 out, 2 bias+gelu -> bf16 out, 3 bias+residual -> fp32 out
// CTA tile 128x128, K-chunk 32, 8 warps (2x4), warp tile 64x32, mma m16n8k16.
// smem rows padded to 40 bf16 (80B) -> conflict-free ldmatrix gathers.
// ---------------------------------------------------------------------------
__device__ __forceinline__ float gelu_exact(float v)
{
    return 0.5f * v * (1.0f + erff(v * 0.70710678118654752f));
}

__device__ __forceinline__ void ldsm4(unsigned& r0, unsigned& r1, unsigned& r2,
                                      unsigned& r3, unsigned addr)
{
    asm volatile("ldmatrix.sync.aligned.m8n8.x4.shared.b16 {%0,%1,%2,%3}, [%4];"
                 : "=r"(r0), "=r"(r1), "=r"(r2), "=r"(r3) : "r"(addr));
}

__device__ __forceinline__ void mma16816(float* c, const unsigned* a,
                                         unsigned b0, unsigned b1)
{
    asm volatile(
        "mma.sync.aligned.m16n8k16.row.col.f32.bf16.bf16.f32 "
        "{%0,%1,%2,%3}, {%4,%5,%6,%7}, {%8,%9}, {%0,%1,%2,%3};"
        : "+f"(c[0]), "+f"(c[1]), "+f"(c[2]), "+f"(c[3])
        : "r"(a[0]), "r"(a[1]), "r"(a[2]), "r"(a[3]), "r"(b0), "r"(b1));
}

#define PADK 40

template <int EPI>
__global__ void __launch_bounds__(256)
hgemm_kernel(int Nd, int Kd,
             const __nv_bfloat16* __restrict__ A,
             const __nv_bfloat16* __restrict__ Bm,
             const float* __restrict__ bias,
             const float* __restrict__ resid,
             void* __restrict__ CoutV)
{
    __shared__ __nv_bfloat16 As[2][128 * PADK];
    __shared__ __nv_bfloat16 Bs[2][128 * PADK];

    int tid  = threadIdx.x;
    int lane = tid & 31;
    int wid  = tid >> 5;
    int wm   = wid >> 2;          // 0..1
    int wn   = wid & 3;           // 0..3
    int m0   = blockIdx.y * 128;
    int n0   = blockIdx.x * 128;

    // global load mapping: 512 chunks of 8 bf16 (16B); 2 per thread
    int ldRow0 = (tid + 0)   >> 2, ldCol0 = ((tid + 0)   & 3) * 8;
    int ldRow1 = (tid + 256) >> 2, ldCol1 = ((tid + 256) & 3) * 8;

    const __nv_bfloat16* Ag0 = A  + (size_t)(m0 + ldRow0) * Kd + ldCol0;
    const __nv_bfloat16* Ag1 = A  + (size_t)(m0 + ldRow1) * Kd + ldCol1;
    const __nv_bfloat16* Bg0 = Bm + (size_t)(n0 + ldRow0) * Kd + ldCol0;
    const __nv_bfloat16* Bg1 = Bm + (size_t)(n0 + ldRow1) * Kd + ldCol1;

    // ldmatrix per-lane offsets
    unsigned aOff = ((wm * 64 + (lane & 15)) * PADK + (lane >> 4) * 8) * 2;
    int g = lane >> 3;
    unsigned bOff = ((((g & 1) * 8 + (lane & 7)) + wn * 32) * PADK + (g >> 1) * 8) * 2;

    float acc[4][4][4];
    #pragma unroll
    for (int i = 0; i < 4; i++)
        #pragma unroll
        for (int j = 0; j < 4; j++)
            #pragma unroll
            for (int r = 0; r < 4; r++) acc[i][j][r] = 0.0f;

    int KT = Kd >> 5;

    // preload tile 0
    {
        uint4 a0 = *(const uint4*)Ag0, a1 = *(const uint4*)Ag1;
        uint4 b0 = *(const uint4*)Bg0, b1 = *(const uint4*)Bg1;
        *(uint4*)(As[0] + ldRow0 * PADK + ldCol0) = a0;
        *(uint4*)(As[0] + ldRow1 * PADK + ldCol1) = a1;
        *(uint4*)(Bs[0] + ldRow0 * PADK + ldCol0) = b0;
        *(uint4*)(Bs[0] + ldRow1 * PADK + ldCol1) = b1;
    }
    __syncthreads();

    int buf = 0;
    for (int t = 0; t < KT; t++) {
        uint4 pa0, pa1, pb0, pb1;
        if (t + 1 < KT) {
            int ko = (t + 1) << 5;
            pa0 = *(const uint4*)(Ag0 + ko);
            pa1 = *(const uint4*)(Ag1 + ko);
            pb0 = *(const uint4*)(Bg0 + ko);
            pb1 = *(const uint4*)(Bg1 + ko);
        }

        unsigned aB = (unsigned)__cvta_generic_to_shared(&As[buf][0]) + aOff;
        unsigned bB = (unsigned)__cvta_generic_to_shared(&Bs[buf][0]) + bOff;

        #pragma unroll
        for (int ks = 0; ks < 2; ks++) {
            unsigned af[4][4];
            #pragma unroll
            for (int mf = 0; mf < 4; mf++)
                ldsm4(af[mf][0], af[mf][1], af[mf][2], af[mf][3],
                      aB + mf * 16 * PADK * 2 + ks * 32);
            unsigned bf[2][4];
            #pragma unroll
            for (int np = 0; np < 2; np++)
                ldsm4(bf[np][0], bf[np][1], bf[np][2], bf[np][3],
                      bB + np * 16 * PADK * 2 + ks * 32);
            #pragma unroll
            for (int mf = 0; mf < 4; mf++) {
                #pragma unroll
                for (int np = 0; np < 2; np++) {
                    mma16816(acc[mf][np * 2 + 0], af[mf], bf[np][0], bf[np][2]);
                    mma16816(acc[mf][np * 2 + 1], af[mf], bf[np][1], bf[np][3]);
                }
            }
        }

        if (t + 1 < KT) {
            int nb = buf ^ 1;
            *(uint4*)(As[nb] + ldRow0 * PADK + ldCol0) = pa0;
            *(uint4*)(As[nb] + ldRow1 * PADK + ldCol1) = pa1;
            *(uint4*)(Bs[nb] + ldRow0 * PADK + ldCol0) = pb0;
            *(uint4*)(Bs[nb] + ldRow1 * PADK + ldCol1) = pb1;
        }
        __syncthreads();
        buf ^= 1;
    }

    // epilogue
    int lr = lane >> 2;
    int lc = (lane & 3) * 2;
    #pragma unroll
    for (int mf = 0; mf < 4; mf++) {
        #pragma unroll
        for (int nf = 0; nf < 4; nf++) {
            int row = m0 + wm * 64 + mf * 16 + lr;
            int col = n0 + wn * 32 + nf * 8 + lc;
            float* c = acc[mf][nf];
            #pragma unroll
            for (int half = 0; half < 2; half++) {
                int r  = row + half * 8;
                float v0 = c[half * 2 + 0];
                float v1 = c[half * 2 + 1];
                size_t off = (size_t)r * Nd + col;
                if (EPI == 0) {
                    ((float2*)((float*)CoutV + off))[0] = make_float2(v0, v1);
                } else if (EPI == 2) {
                    v0 = gelu_exact(v0 + bias[col]);
                    v1 = gelu_exact(v1 + bias[col + 1]);
                    __nv_bfloat162 bv = __float22bfloat162_rn(make_float2(v0, v1));
                    *(unsigned*)((__nv_bfloat16*)CoutV + off) = __bf2u(bv);
                } else { // EPI == 3
                    v0 += bias[col]     + resid[off];
                    v1 += bias[col + 1] + resid[off + 1];
                    ((float2*)((float*)CoutV + off))[0] = make_float2(v0, v1);
                }
            }
        }
    }
}

// ---------------------------------------------------------------------------
// Windowed attention + fused LePE (fp32, unchanged math; bf16 output)
// One CTA per (branch, window, head): 512 queries x 512 keys x hd=16.
// ---------------------------------------------------------------------------
#define ATT_SMEM_FLOATS (2 * 512 * 17 + 16 * 27 + 16)

__global__ void __launch_bounds__(256, 1)
attn_kernel(const float* __restrict__ qkv,
            const float* __restrict__ conv_w0, const float* __restrict__ conv_b0,
            const float* __restrict__ conv_w1, const float* __restrict__ conv_b1)
{
    extern __shared__ float smem[];
    float* ks = smem;                    // [512][17]
    float* vs = smem + 512 * 17;         // [512][17]
    float* cw = vs + 512 * 17;           // [16][27]
    float* cb = cw + 16 * 27;            // [16]

    int cta    = blockIdx.x;
    int branch = cta >> 8;
    int rem    = cta & 255;
    int win    = rem >> 2;
    int head   = rem & 3;

    int Hsp   = branch ? 4 : 32;
    int Wsp   = branch ? 32 : 4;
    int lw    = branch ? 5 : 2;
    int wmask = Wsp - 1;
    int nWh   = branch ? 8 : 1;
    int nWw   = branch ? 1 : 8;
    int nwin  = nWh * nWw;

    int bidx = win >> 4;
    int wrem = win & 15;
    int wt = wrem / nwin;
    int wsp = wrem % nwin;
    int wh = wsp / nWw;
    int ww = wsp % nWw;

    int choff = branch * 64 + head * 16;
    int tid = threadIdx.x;

    #define WIN_L(p, itv, ihv, iwv)                                     \
        int itv = (p) >> 7;                                             \
        int _r  = (p) & 127;                                            \
        int ihv = _r >> lw;                                             \
        int iwv = _r & wmask;                                           \
        int _t  = wt * 4 + itv;                                         \
        int _h  = wh * Hsp + ihv;                                       \
        int _w  = ww * Wsp + iwv;                                       \
        int lrow = bidx * LL + (_t << 10) + (_h << 5) + _w;

    for (int p = tid; p < 512; p += 256) {
        WIN_L(p, it_, ih_, iw_);
        (void)it_; (void)ih_; (void)iw_;
        const float* kp = qkv + (size_t)lrow * 384 + 128 + choff;
        const float* vp = qkv + (size_t)lrow * 384 + 256 + choff;
        float4 k0 = ((const float4*)kp)[0], k1 = ((const float4*)kp)[1];
        float4 k2 = ((const float4*)kp)[2], k3 = ((const float4*)kp)[3];
        float4 v0 = ((const float4*)vp)[0], v1 = ((const float4*)vp)[1];
        float4 v2 = ((const float4*)vp)[2], v3 = ((const float4*)vp)[3];
        float* kd = ks + p * 17;
        float* vd = vs + p * 17;
        kd[0]=k0.x; kd[1]=k0.y; kd[2]=k0.z; kd[3]=k0.w;
        kd[4]=k1.x; kd[5]=k1.y; kd[6]=k1.z; kd[7]=k1.w;
        kd[8]=k2.x; kd[9]=k2.y; kd[10]=k2.z; kd[11]=k2.w;
        kd[12]=k3.x; kd[13]=k3.y; kd[14]=k3.z; kd[15]=k3.w;
        vd[0]=v0.x; vd[1]=v0.y; vd[2]=v0.z; vd[3]=v0.w;
        vd[4]=v1.x; vd[5]=v1.y; vd[6]=v1.z; vd[7]=v1.w;
        vd[8]=v2.x; vd[9]=v2.y; vd[10]=v2.z; vd[11]=v2.w;
        vd[12]=v3.x; vd[13]=v3.y; vd[14]=v3.z; vd[15]=v3.w;
    }
    const float* cwp = branch ? conv_w1 : conv_w0;
    const float* cbp = branch ? conv_b1 : conv_b0;
    for (int i = tid; i < 16 * 27; i += 256) cw[i] = cwp[head * 16 * 27 + i];
    if (tid < 16) cb[tid] = cbp[head * 16 + tid];

    int p0 = tid, p1 = tid + 256;
    float q0[16], q1[16];
    int row0, row1;
    {
        WIN_L(p0, a, b_, c); (void)a; (void)b_; (void)c;
        row0 = lrow;
        const float4* qp = (const float4*)(qkv + (size_t)lrow * 384 + choff);
        float4 t0 = qp[0], t1 = qp[1], t2 = qp[2], t3 = qp[3];
        q0[0]=t0.x*0.25f; q0[1]=t0.y*0.25f; q0[2]=t0.z*0.25f; q0[3]=t0.w*0.25f;
        q0[4]=t1.x*0.25f; q0[5]=t1.y*0.25f; q0[6]=t1.z*0.25f; q0[7]=t1.w*0.25f;
        q0[8]=t2.x*0.25f; q0[9]=t2.y*0.25f; q0[10]=t2.z*0.25f; q0[11]=t2.w*0.25f;
        q0[12]=t3.x*0.25f; q0[13]=t3.y*0.25f; q0[14]=t3.z*0.25f; q0[15]=t3.w*0.25f;
    }
    {
        WIN_L(p1, a, b_, c); (void)a; (void)b_; (void)c;
        row1 = lrow;
        const float4* qp = (const float4*)(qkv + (size_t)lrow * 384 + choff);
        float4 t0 = qp[0], t1 = qp[1], t2 = qp[2], t3 = qp[3];
        q1[0]=t0.x*0.25f; q1[1]=t0.y*0.25f; q1[2]=t0.z*0.25f; q1[3]=t0.w*0.25f;
        q1[4]=t1.x*0.25f; q1[5]=t1.y*0.25f; q1[6]=t1.z*0.25f; q1[7]=t1.w*0.25f;
        q1[8]=t2.x*0.25f; q1[9]=t2.y*0.25f; q1[10]=t2.z*0.25f; q1[11]=t2.w*0.25f;
        q1[12]=t3.x*0.25f; q1[13]=t3.y*0.25f; q1[14]=t3.z*0.25f; q1[15]=t3.w*0.25f;
    }
    __syncthreads();

    float acc0[16], acc1[16];
    #pragma unroll
    for (int d = 0; d < 16; d++) { acc0[d] = 0.0f; acc1[d] = 0.0f; }
    float sum0 = 0.0f, sum1 = 0.0f;

    for (int j = 0; j < 512; j++) {
        const float* kj = ks + j * 17;
        float s0 = 0.0f, s1 = 0.0f;
        #pragma unroll
        for (int d = 0; d < 16; d++) {
            float kk = kj[d];
            s0 += q0[d] * kk;
            s1 += q1[d] * kk;
        }
        float e0 = __expf(fminf(s0, 30.0f));
        float e1 = __expf(fminf(s1, 30.0f));
        sum0 += e0; sum1 += e1;
        const float* vj = vs + j * 17;
        #pragma unroll
        for (int d = 0; d < 16; d++) {
            float vv = vj[d];
            acc0[d] += e0 * vv;
            acc1[d] += e1 * vv;
        }
    }

    float inv0 = 1.0f / sum0;
    float inv1 = 1.0f / sum1;
    float o0[16], o1[16];
    #pragma unroll
    for (int d = 0; d < 16; d++) {
        o0[d] = acc0[d] * inv0 + cb[d];
        o1[d] = acc1[d] * inv1 + cb[d];
    }

    {
        int it0 = p0 >> 7; int r0_ = p0 & 127; int ih0 = r0_ >> lw; int iw0 = r0_ & wmask;
        int it1 = p1 >> 7; int r1_ = p1 & 127; int ih1 = r1_ >> lw; int iw1 = r1_ & wmask;
        #pragma unroll
        for (int dz = 0; dz < 3; dz++) {
            #pragma unroll
            for (int dy = 0; dy < 3; dy++) {
                #pragma unroll
                for (int dx = 0; dx < 3; dx++) {
                    int widx = dz * 9 + dy * 3 + dx;
                    {
                        int z = it0 + dz - 1, y = ih0 + dy - 1, x = iw0 + dx - 1;
                        if (z >= 0 && z < 4 && y >= 0 && y < Hsp && x >= 0 && x < Wsp) {
                            const float* vsrc = vs + (((z << 7) + (y << lw) + x) * 17);
                            #pragma unroll
                            for (int d = 0; d < 16; d++)
                                o0[d] += cw[d * 27 + widx] * vsrc[d];
                        }
                    }
                    {
                        int z = it1 + dz - 1, y = ih1 + dy - 1, x = iw1 + dx - 1;
                        if (z >= 0 && z < 4 && y >= 0 && y < Hsp && x >= 0 && x < Wsp) {
                            const float* vsrc = vs + (((z << 7) + (y << lw) + x) * 17);
                            #pragma unroll
                            for (int d = 0; d < 16; d++)
                                o1[d] += cw[d * 27 + widx] * vsrc[d];
                        }
                    }
                }
            }
        }
    }

    // scatter (bf16) to concat channel layout
    {
        uint4 u, w;
        u.x = __bf2u(__float22bfloat162_rn(make_float2(o0[0], o0[1])));
        u.y = __bf2u(__float22bfloat162_rn(make_float2(o0[2], o0[3])));
        u.z = __bf2u(__float22bfloat162_rn(make_float2(o0[4], o0[5])));
        u.w = __bf2u(__float22bfloat162_rn(make_float2(o0[6], o0[7])));
        w.x = __bf2u(__float22bfloat162_rn(make_float2(o0[8], o0[9])));
        w.y = __bf2u(__float22bfloat162_rn(make_float2(o0[10], o0[11])));
        w.z = __bf2u(__float22bfloat162_rn(make_float2(o0[12], o0[13])));
        w.w = __bf2u(__float22bfloat162_rn(make_float2(o0[14], o0[15])));
        uint4* op = (uint4*)(g_att + (size_t)row0 * CC + choff);
        op[0] = u; op[1] = w;
    }
    {
        uint4 u, w;
        u.x = __bf2u(__float22bfloat162_rn(make_float2(o1[0], o1[1])));
        u.y = __bf2u(__float22bfloat162_rn(make_float2(o1[2], o1[3])));
        u.z = __bf2u(__float22bfloat162_rn(make_float2(o1[4], o1[5])));
        u.w = __bf2u(__float22bfloat162_rn(make_float2(o1[6], o1[7])));
        w.x = __bf2u(__float22bfloat162_rn(make_float2(o1[8], o1[9])));
        w.y = __bf2u(__float22bfloat162_rn(make_float2(o1[10], o1[11])));
        w.z = __bf2u(__float22bfloat162_rn(make_float2(o1[12], o1[13])));
        w.w = __bf2u(__float22bfloat162_rn(make_float2(o1[14], o1[15])));
        uint4* op = (uint4*)(g_att + (size_t)row1 * CC + choff);
        op[0] = u; op[1] = w;
    }
    #undef WIN_L
}

// ---------------------------------------------------------------------------
// Launch
// ---------------------------------------------------------------------------
extern "C" void kernel_launch(void* const* d_in, const int* in_sizes, int n_in,
                              void* d_out, int out_size)
{
    const float* x       = (const float*)d_in[0];
    const float* norm1_w = (const float*)d_in[1];
    const float* norm1_b = (const float*)d_in[2];
    const float* qkv_w   = (const float*)d_in[3];
    const float* conv_w0 = (const float*)d_in[4];
    const float* conv_b0 = (const float*)d_in[5];
    const float* conv_w1 = (const float*)d_in[6];
    const float* conv_b1 = (const float*)d_in[7];
    const float* proj_w  = (const float*)d_in[8];
    const float* proj_b  = (const float*)d_in[9];
    const float* norm2_w = (const float*)d_in[10];
    const float* norm2_b = (const float*)d_in[11];
    const float* fc1_w   = (const float*)d_in[12];
    const float* fc1_b   = (const float*)d_in[13];
    const float* fc2_w   = (const float*)d_in[14];
    const float* fc2_b   = (const float*)d_in[15];
    float* out = (float*)d_out;

    __nv_bfloat16 *p_img, *p_att, *p_y, *p_hid;
    __nv_bfloat16 *p_wqkv, *p_wproj, *p_wfc1, *p_wfc2;
    float *p_qkv, *p_x2;
    cudaGetSymbolAddress((void**)&p_img, g_img);
    cudaGetSymbolAddress((void**)&p_qkv, g_qkv);
    cudaGetSymbolAddress((void**)&p_att, g_att);
    cudaGetSymbolAddress((void**)&p_x2,  g_x2);
    cudaGetSymbolAddress((void**)&p_y,   g_y);
    cudaGetSymbolAddress((void**)&p_hid, g_hid);
    cudaGetSymbolAddress((void**)&p_wqkv,  g_wqkv);
    cudaGetSymbolAddress((void**)&p_wproj, g_wproj);
    cudaGetSymbolAddress((void**)&p_wfc1,  g_wfc1);
    cudaGetSymbolAddress((void**)&p_wfc2,  g_wfc2);

    int att_smem = ATT_SMEM_FLOATS * (int)sizeof(float);
    cudaFuncSetAttribute(attn_kernel,
                         cudaFuncAttributeMaxDynamicSharedMemorySize, att_smem);

    dim3 lnBlock(32, 8);

    // 0. weights -> bf16
    convert_weights<<<768, 256>>>(qkv_w, proj_w, fc1_w, fc2_w);

    // 1. LN1 -> bf16
    ln_kernel<<<MROWS / 8, lnBlock>>>(x, norm1_w, norm1_b, p_img);

    // 2. QKV GEMM  (32768 x 384 x 128), fp32 out
    hgemm_kernel<0><<<dim3(3, MROWS / 128), 256>>>(
        384, 128, p_img, p_wqkv, nullptr, nullptr, p_qkv);

    // 3. Attention + LePE -> bf16 att
    attn_kernel<<<512, 256, att_smem>>>(p_qkv, conv_w0, conv_b0, conv_w1, conv_b1);

    // 4. proj + bias + residual(x) -> x2 (fp32)
    hgemm_kernel<3><<<dim3(1, MROWS / 128), 256>>>(
        128, 128, p_att, p_wproj, proj_b, x, p_x2);

    // 5. LN2 -> bf16
    ln_kernel<<<MROWS / 8, lnBlock>>>(p_x2, norm2_w, norm2_b, p_y);

    // 6. fc1 + bias + gelu -> bf16 hid
    hgemm_kernel<2><<<dim3(4, MROWS / 128), 256>>>(
        512, 128, p_y, p_wfc1, fc1_b, nullptr, p_hid);

    // 7. fc2 + bias + residual(x2) -> out (fp32)
    hgemm_kernel<3><<<dim3(1, MROWS / 128), 256>>>(
        128, 512, p_hid, p_wfc2, fc2_b, p_x2, out);
}

// round 13
// speedup vs baseline: 5.9997x; 2.0230x over previous
#include <cuda_runtime.h>
#include <cuda_bf16.h>
#include <math.h>

// ---------------------------------------------------------------------------
// Problem constants
// ---------------------------------------------------------------------------
#define BB     4
#define TT     8
#define RESO   32
#define CC     128
#define LL     (TT * RESO * RESO)     // 8192
#define MROWS  (BB * LL)              // 32768
#define HID    (4 * CC)               // 512

// ---------------------------------------------------------------------------
// Device scratch
// ---------------------------------------------------------------------------
__device__ __nv_bfloat16 g_img[(size_t)MROWS * CC];       // LN1 output (bf16)
__device__ __nv_bfloat16 g_qkv[(size_t)MROWS * 3 * CC];   // qkv (bf16)
__device__ __nv_bfloat16 g_att[(size_t)MROWS * CC];       // attention output (bf16)
__device__ float         g_x2 [(size_t)MROWS * CC];       // x + proj(att)  (fp32)
__device__ __nv_bfloat16 g_y  [(size_t)MROWS * CC];       // LN2 output (bf16)
__device__ __nv_bfloat16 g_hid[(size_t)MROWS * HID];      // gelu(fc1) (bf16)

__device__ __nv_bfloat16 g_wqkv[384 * 128];
__device__ __nv_bfloat16 g_wproj[128 * 128];
__device__ __nv_bfloat16 g_wfc1[512 * 128];
__device__ __nv_bfloat16 g_wfc2[128 * 512];

// bit-cast helper
__device__ __forceinline__ unsigned __bf2u(__nv_bfloat162 v)
{
    return *(unsigned*)&v;
}
__device__ __forceinline__ unsigned packbf(float lo, float hi)
{
    return __bf2u(__float22bfloat162_rn(make_float2(lo, hi)));
}

// ---------------------------------------------------------------------------
// Weight fp32 -> bf16 conversion
// ---------------------------------------------------------------------------
__global__ void convert_weights(const float* __restrict__ qkvw,
                                const float* __restrict__ projw,
                                const float* __restrict__ fc1w,
                                const float* __restrict__ fc2w)
{
    int i = blockIdx.x * 256 + threadIdx.x;
    if (i < 49152)       g_wqkv[i]           = __float2bfloat16(qkvw[i]);
    else if (i < 65536)  g_wproj[i - 49152]  = __float2bfloat16(projw[i - 49152]);
    else if (i < 131072) g_wfc1[i - 65536]   = __float2bfloat16(fc1w[i - 65536]);
    else if (i < 196608) g_wfc2[i - 131072]  = __float2bfloat16(fc2w[i - 131072]);
}

// ---------------------------------------------------------------------------
// LayerNorm: one warp per token, bf16 output
// ---------------------------------------------------------------------------
__global__ void ln_kernel(const float* __restrict__ x,
                          const float* __restrict__ w,
                          const float* __restrict__ b,
                          __nv_bfloat16* __restrict__ out)
{
    int row  = blockIdx.x * 8 + threadIdx.y;
    int lane = threadIdx.x;
    const float4* rp = (const float4*)(x + (size_t)row * CC);
    float4 v = rp[lane];
    float s  = v.x + v.y + v.z + v.w;
    float ss = v.x * v.x + v.y * v.y + v.z * v.z + v.w * v.w;
    #pragma unroll
    for (int o = 16; o > 0; o >>= 1) {
        s  += __shfl_xor_sync(0xffffffffu, s,  o);
        ss += __shfl_xor_sync(0xffffffffu, ss, o);
    }
    float mean = s * (1.0f / CC);
    float var  = ss * (1.0f / CC) - mean * mean;
    float rstd = rsqrtf(var + 1e-5f);
    float4 wv = ((const float4*)w)[lane];
    float4 bv = ((const float4*)b)[lane];
    uint2 u;
    u.x = packbf((v.x - mean) * rstd * wv.x + bv.x, (v.y - mean) * rstd * wv.y + bv.y);
    u.y = packbf((v.z - mean) * rstd * wv.z + bv.z, (v.w - mean) * rstd * wv.w + bv.w);
    ((uint2*)(out + (size_t)row * CC))[lane] = u;
}

// ---------------------------------------------------------------------------
// mma / ldmatrix helpers
// ---------------------------------------------------------------------------
__device__ __forceinline__ float gelu_exact(float v)
{
    return 0.5f * v * (1.0f + erff(v * 0.70710678118654752f));
}

__device__ __forceinline__ void ldsm4(unsigned& r0, unsigned& r1, unsigned& r2,
                                      unsigned& r3, unsigned addr)
{
    asm volatile("ldmatrix.sync.aligned.m8n8.x4.shared.b16 {%0,%1,%2,%3}, [%4];"
                 : "=r"(r0), "=r"(r1), "=r"(r2), "=r"(r3) : "r"(addr));
}

__device__ __forceinline__ void mma16816(float* c, const unsigned* a,
                                         unsigned b0, unsigned b1)
{
    asm volatile(
        "mma.sync.aligned.m16n8k16.row.col.f32.bf16.bf16.f32 "
        "{%0,%1,%2,%3}, {%4,%5,%6,%7}, {%8,%9}, {%0,%1,%2,%3};"
        : "+f"(c[0]), "+f"(c[1]), "+f"(c[2]), "+f"(c[3])
        : "r"(a[0]), "r"(a[1]), "r"(a[2]), "r"(a[3]), "r"(b0), "r"(b1));
}

// ---------------------------------------------------------------------------
// bf16 tensor-core GEMM (unchanged core; EPI 0 now stores bf16)
// ---------------------------------------------------------------------------
#define PADK 40

template <int EPI>
__global__ void __launch_bounds__(256)
hgemm_kernel(int Nd, int Kd,
             const __nv_bfloat16* __restrict__ A,
             const __nv_bfloat16* __restrict__ Bm,
             const float* __restrict__ bias,
             const float* __restrict__ resid,
             void* __restrict__ CoutV)
{
    __shared__ __nv_bfloat16 As[2][128 * PADK];
    __shared__ __nv_bfloat16 Bs[2][128 * PADK];

    int tid  = threadIdx.x;
    int lane = tid & 31;
    int wid  = tid >> 5;
    int wm   = wid >> 2;
    int wn   = wid & 3;
    int m0   = blockIdx.y * 128;
    int n0   = blockIdx.x * 128;

    int ldRow0 = (tid + 0)   >> 2, ldCol0 = ((tid + 0)   & 3) * 8;
    int ldRow1 = (tid + 256) >> 2, ldCol1 = ((tid + 256) & 3) * 8;

    const __nv_bfloat16* Ag0 = A  + (size_t)(m0 + ldRow0) * Kd + ldCol0;
    const __nv_bfloat16* Ag1 = A  + (size_t)(m0 + ldRow1) * Kd + ldCol1;
    const __nv_bfloat16* Bg0 = Bm + (size_t)(n0 + ldRow0) * Kd + ldCol0;
    const __nv_bfloat16* Bg1 = Bm + (size_t)(n0 + ldRow1) * Kd + ldCol1;

    unsigned aOff = ((wm * 64 + (lane & 15)) * PADK + (lane >> 4) * 8) * 2;
    int g = lane >> 3;
    unsigned bOff = ((((g & 1) * 8 + (lane & 7)) + wn * 32) * PADK + (g >> 1) * 8) * 2;

    float acc[4][4][4];
    #pragma unroll
    for (int i = 0; i < 4; i++)
        #pragma unroll
        for (int j = 0; j < 4; j++)
            #pragma unroll
            for (int r = 0; r < 4; r++) acc[i][j][r] = 0.0f;

    int KT = Kd >> 5;

    {
        uint4 a0 = *(const uint4*)Ag0, a1 = *(const uint4*)Ag1;
        uint4 b0 = *(const uint4*)Bg0, b1 = *(const uint4*)Bg1;
        *(uint4*)(As[0] + ldRow0 * PADK + ldCol0) = a0;
        *(uint4*)(As[0] + ldRow1 * PADK + ldCol1) = a1;
        *(uint4*)(Bs[0] + ldRow0 * PADK + ldCol0) = b0;
        *(uint4*)(Bs[0] + ldRow1 * PADK + ldCol1) = b1;
    }
    __syncthreads();

    int buf = 0;
    for (int t = 0; t < KT; t++) {
        uint4 pa0, pa1, pb0, pb1;
        if (t + 1 < KT) {
            int ko = (t + 1) << 5;
            pa0 = *(const uint4*)(Ag0 + ko);
            pa1 = *(const uint4*)(Ag1 + ko);
            pb0 = *(const uint4*)(Bg0 + ko);
            pb1 = *(const uint4*)(Bg1 + ko);
        }

        unsigned aB = (unsigned)__cvta_generic_to_shared(&As[buf][0]) + aOff;
        unsigned bB = (unsigned)__cvta_generic_to_shared(&Bs[buf][0]) + bOff;

        #pragma unroll
        for (int ks = 0; ks < 2; ks++) {
            unsigned af[4][4];
            #pragma unroll
            for (int mf = 0; mf < 4; mf++)
                ldsm4(af[mf][0], af[mf][1], af[mf][2], af[mf][3],
                      aB + mf * 16 * PADK * 2 + ks * 32);
            unsigned bfr[2][4];
            #pragma unroll
            for (int np = 0; np < 2; np++)
                ldsm4(bfr[np][0], bfr[np][1], bfr[np][2], bfr[np][3],
                      bB + np * 16 * PADK * 2 + ks * 32);
            #pragma unroll
            for (int mf = 0; mf < 4; mf++) {
                #pragma unroll
                for (int np = 0; np < 2; np++) {
                    mma16816(acc[mf][np * 2 + 0], af[mf], bfr[np][0], bfr[np][2]);
                    mma16816(acc[mf][np * 2 + 1], af[mf], bfr[np][1], bfr[np][3]);
                }
            }
        }

        if (t + 1 < KT) {
            int nb = buf ^ 1;
            *(uint4*)(As[nb] + ldRow0 * PADK + ldCol0) = pa0;
            *(uint4*)(As[nb] + ldRow1 * PADK + ldCol1) = pa1;
            *(uint4*)(Bs[nb] + ldRow0 * PADK + ldCol0) = pb0;
            *(uint4*)(Bs[nb] + ldRow1 * PADK + ldCol1) = pb1;
        }
        __syncthreads();
        buf ^= 1;
    }

    int lr = lane >> 2;
    int lc = (lane & 3) * 2;
    #pragma unroll
    for (int mf = 0; mf < 4; mf++) {
        #pragma unroll
        for (int nf = 0; nf < 4; nf++) {
            int row = m0 + wm * 64 + mf * 16 + lr;
            int col = n0 + wn * 32 + nf * 8 + lc;
            float* c = acc[mf][nf];
            #pragma unroll
            for (int half = 0; half < 2; half++) {
                int r  = row + half * 8;
                float v0 = c[half * 2 + 0];
                float v1 = c[half * 2 + 1];
                size_t off = (size_t)r * Nd + col;
                if (EPI == 0) {
                    *(unsigned*)((__nv_bfloat16*)CoutV + off) = packbf(v0, v1);
                } else if (EPI == 2) {
                    v0 = gelu_exact(v0 + bias[col]);
                    v1 = gelu_exact(v1 + bias[col + 1]);
                    *(unsigned*)((__nv_bfloat16*)CoutV + off) = packbf(v0, v1);
                } else { // EPI == 3
                    v0 += bias[col]     + resid[off];
                    v1 += bias[col + 1] + resid[off + 1];
                    ((float2*)((float*)CoutV + off))[0] = make_float2(v0, v1);
                }
            }
        }
    }
}

// ---------------------------------------------------------------------------
// Tensor-core windowed attention + fused LePE.
// One CTA per (branch, window, head): 512 q x 512 k, hd=16, bf16 mma.
// 8 warps; warp w owns q rows [w*64, w*64+64).
// K smem [512][24] bf16; V smem transposed [16][520] bf16 (mma B + conv gathers).
// ---------------------------------------------------------------------------
__global__ void __launch_bounds__(256, 1)
attn_mma_kernel(const __nv_bfloat16* __restrict__ qkv,
                const float* __restrict__ conv_w0, const float* __restrict__ conv_b0,
                const float* __restrict__ conv_w1, const float* __restrict__ conv_b1)
{
    __shared__ __nv_bfloat16 Ks[512 * 24];
    __shared__ __nv_bfloat16 Vt[16 * 520];
    __shared__ float cw[16 * 27];
    __shared__ float cb[16];

    int cta    = blockIdx.x;
    int branch = cta >> 8;
    int rem    = cta & 255;
    int win    = rem >> 2;
    int head   = rem & 3;

    int Hsp   = branch ? 4 : 32;
    int Wsp   = branch ? 32 : 4;
    int lw    = branch ? 5 : 2;
    int wmask = Wsp - 1;
    int nWw   = branch ? 1 : 8;

    int bidx = win >> 4;
    int wrem = win & 15;
    int wt   = wrem >> 3;          // nwin == 8 always
    int wsp  = wrem & 7;
    int wh   = wsp / nWw;
    int ww   = wsp % nWw;

    int choff = branch * 64 + head * 16;
    int tid  = threadIdx.x;
    int lane = tid & 31;
    int warp = tid >> 5;

    // window position p -> global token row
    #define ROW_OF(p, itv, ihv, iwv, lrowv)                              \
        int itv = (p) >> 7;                                              \
        int ihv = ((p) & 127) >> lw;                                     \
        int iwv = (p) & wmask;                                           \
        int lrowv = bidx * LL + ((wt * 4 + itv) << 10)                   \
                  + ((wh * Hsp + ihv) << 5) + (ww * Wsp + iwv);

    // ---- stage K (row-major, pad 24) and V (transposed [16][520]) ----
    for (int p = tid; p < 512; p += 256) {
        ROW_OF(p, a_, b_, c_, lrow); (void)a_; (void)b_; (void)c_;
        const uint4* kp = (const uint4*)(qkv + (size_t)lrow * 384 + 128 + choff);
        uint4 k0 = kp[0], k1 = kp[1];
        *(uint4*)(Ks + p * 24 + 0) = k0;
        *(uint4*)(Ks + p * 24 + 8) = k1;
        const uint4* vp = (const uint4*)(qkv + (size_t)lrow * 384 + 256 + choff);
        uint4 v0 = vp[0], v1 = vp[1];
        __nv_bfloat16 vtmp[16];
        *(uint4*)(vtmp + 0) = v0;
        *(uint4*)(vtmp + 8) = v1;
        #pragma unroll
        for (int d = 0; d < 16; d++) Vt[d * 520 + p] = vtmp[d];
    }
    const float* cwp = branch ? conv_w1 : conv_w0;
    const float* cbp = branch ? conv_b1 : conv_b0;
    for (int i = tid; i < 16 * 27; i += 256) cw[i] = cwp[head * 432 + i];
    if (tid < 16) cb[tid] = cbp[head * 16 + tid];

    // ---- Q a-frags, loaded directly from global, scaled by 0.25 ----
    int qr = lane >> 2;
    int qc = (lane & 3) * 2;
    __nv_bfloat162 qscale = __float2bfloat162_rn(0.25f);
    unsigned qa[4][4];
    #pragma unroll
    for (int mt = 0; mt < 4; mt++) {
        int pr0 = warp * 64 + mt * 16 + qr;
        int pr1 = pr0 + 8;
        ROW_OF(pr0, a0_, b0_, c0_, lrow0); (void)a0_; (void)b0_; (void)c0_;
        ROW_OF(pr1, a1_, b1_, c1_, lrow1); (void)a1_; (void)b1_; (void)c1_;
        const __nv_bfloat16* q0p = qkv + (size_t)lrow0 * 384 + choff;
        const __nv_bfloat16* q1p = qkv + (size_t)lrow1 * 384 + choff;
        __nv_bfloat162 t;
        t = __hmul2(*(const __nv_bfloat162*)(q0p + qc),     qscale); qa[mt][0] = __bf2u(t);
        t = __hmul2(*(const __nv_bfloat162*)(q1p + qc),     qscale); qa[mt][1] = __bf2u(t);
        t = __hmul2(*(const __nv_bfloat162*)(q0p + qc + 8), qscale); qa[mt][2] = __bf2u(t);
        t = __hmul2(*(const __nv_bfloat162*)(q1p + qc + 8), qscale); qa[mt][3] = __bf2u(t);
    }
    __syncthreads();

    // ---- streaming attention over 16 k-tiles of 32 keys ----
    float oAcc[4][2][4];
    #pragma unroll
    for (int mt = 0; mt < 4; mt++)
        #pragma unroll
        for (int nf = 0; nf < 2; nf++)
            #pragma unroll
            for (int r = 0; r < 4; r++) oAcc[mt][nf][r] = 0.0f;
    float rsum[4][2];
    #pragma unroll
    for (int mt = 0; mt < 4; mt++) { rsum[mt][0] = 0.0f; rsum[mt][1] = 0.0f; }

    int g = lane >> 3;
    unsigned ksBase = (unsigned)__cvta_generic_to_shared(Ks);
    unsigned vtBase = (unsigned)__cvta_generic_to_shared(Vt);
    unsigned kRowOff = ((g & 1) * 8 + (lane & 7)) * 24 * 2 + (g >> 1) * 8 * 2;
    unsigned vRowOff = ((g & 1) * 8 + (lane & 7)) * 520 * 2 + (g >> 1) * 8 * 2;

    for (int kt = 0; kt < 16; kt++) {
        // K b-frags: 4 n-frags of 8 keys
        unsigned kb[4][2];
        {
            unsigned u0, u1, u2, u3;
            unsigned base = ksBase + kt * 32 * 24 * 2 + kRowOff;
            ldsm4(u0, u1, u2, u3, base);
            kb[0][0] = u0; kb[0][1] = u2; kb[1][0] = u1; kb[1][1] = u3;
            ldsm4(u0, u1, u2, u3, base + 16 * 24 * 2);
            kb[2][0] = u0; kb[2][1] = u2; kb[3][0] = u1; kb[3][1] = u3;
        }
        // V b-frags: [ks0 hd0-7, ks0 hd8-15, ks1 hd0-7, ks1 hd8-15]
        unsigned vb[4][2];
        {
            unsigned u0, u1, u2, u3;
            unsigned base = vtBase + kt * 32 * 2 + vRowOff;
            ldsm4(u0, u1, u2, u3, base);
            vb[0][0] = u0; vb[0][1] = u2; vb[1][0] = u1; vb[1][1] = u3;
            ldsm4(u0, u1, u2, u3, base + 16 * 2);
            vb[2][0] = u0; vb[2][1] = u2; vb[3][0] = u1; vb[3][1] = u3;
        }

        #pragma unroll
        for (int mt = 0; mt < 4; mt++) {
            float s[4][4];
            #pragma unroll
            for (int nf = 0; nf < 4; nf++) {
                s[nf][0] = 0.0f; s[nf][1] = 0.0f; s[nf][2] = 0.0f; s[nf][3] = 0.0f;
                mma16816(s[nf], qa[mt], kb[nf][0], kb[nf][1]);
            }
            // exp + row sums
            #pragma unroll
            for (int nf = 0; nf < 4; nf++) {
                #pragma unroll
                for (int e = 0; e < 4; e++) {
                    float v = __expf(fminf(s[nf][e], 30.0f));
                    s[nf][e] = v;
                    rsum[mt][e >> 1] += v;
                }
            }
            // pack P -> a-frags (2 k-steps of 16 keys)
            unsigned pa0[4], pa1[4];
            pa0[0] = packbf(s[0][0], s[0][1]);
            pa0[1] = packbf(s[0][2], s[0][3]);
            pa0[2] = packbf(s[1][0], s[1][1]);
            pa0[3] = packbf(s[1][2], s[1][3]);
            pa1[0] = packbf(s[2][0], s[2][1]);
            pa1[1] = packbf(s[2][2], s[2][3]);
            pa1[2] = packbf(s[3][0], s[3][1]);
            pa1[3] = packbf(s[3][2], s[3][3]);
            // PV
            mma16816(oAcc[mt][0], pa0, vb[0][0], vb[0][1]);
            mma16816(oAcc[mt][1], pa0, vb[1][0], vb[1][1]);
            mma16816(oAcc[mt][0], pa1, vb[2][0], vb[2][1]);
            mma16816(oAcc[mt][1], pa1, vb[3][0], vb[3][1]);
        }
    }

    // ---- finish row sums (reduce over the 4 lanes of each quad) ----
    #pragma unroll
    for (int mt = 0; mt < 4; mt++) {
        #pragma unroll
        for (int h = 0; h < 2; h++) {
            float s = rsum[mt][h];
            s += __shfl_xor_sync(0xffffffffu, s, 1);
            s += __shfl_xor_sync(0xffffffffu, s, 2);
            rsum[mt][h] = 1.0f / s;
        }
    }

    // ---- epilogue: 1/sum, conv bias, fused LePE gather, store ----
    #pragma unroll
    for (int mt = 0; mt < 4; mt++) {
        #pragma unroll
        for (int h = 0; h < 2; h++) {
            int p = warp * 64 + mt * 16 + qr + h * 8;
            ROW_OF(p, it, ih, iw, lrow);
            float inv = rsum[mt][h];
            int d0 = qc, d2 = qc + 8;
            float a0 = oAcc[mt][0][h * 2 + 0] * inv + cb[d0];
            float a1 = oAcc[mt][0][h * 2 + 1] * inv + cb[d0 + 1];
            float a2 = oAcc[mt][1][h * 2 + 0] * inv + cb[d2];
            float a3 = oAcc[mt][1][h * 2 + 1] * inv + cb[d2 + 1];

            #pragma unroll
            for (int dz = 0; dz < 3; dz++) {
                int z = it + dz - 1;
                if (z < 0 || z >= 4) continue;
                #pragma unroll
                for (int dy = 0; dy < 3; dy++) {
                    int y = ih + dy - 1;
                    if (y < 0 || y >= Hsp) continue;
                    #pragma unroll
                    for (int dx = 0; dx < 3; dx++) {
                        int x = iw + dx - 1;
                        if (x < 0 || x >= Wsp) continue;
                        int widx = dz * 9 + dy * 3 + dx;
                        int pos = (z << 7) + (y << lw) + x;
                        a0 += cw[d0 * 27 + widx]       * __bfloat162float(Vt[d0 * 520 + pos]);
                        a1 += cw[(d0 + 1) * 27 + widx] * __bfloat162float(Vt[(d0 + 1) * 520 + pos]);
                        a2 += cw[d2 * 27 + widx]       * __bfloat162float(Vt[d2 * 520 + pos]);
                        a3 += cw[(d2 + 1) * 27 + widx] * __bfloat162float(Vt[(d2 + 1) * 520 + pos]);
                    }
                }
            }
            __nv_bfloat16* op = g_att + (size_t)lrow * CC + choff;
            *(unsigned*)(op + d0) = packbf(a0, a1);
            *(unsigned*)(op + d2) = packbf(a2, a3);
        }
    }
    #undef ROW_OF
}

// ---------------------------------------------------------------------------
// Launch
// ---------------------------------------------------------------------------
extern "C" void kernel_launch(void* const* d_in, const int* in_sizes, int n_in,
                              void* d_out, int out_size)
{
    const float* x       = (const float*)d_in[0];
    const float* norm1_w = (const float*)d_in[1];
    const float* norm1_b = (const float*)d_in[2];
    const float* qkv_w   = (const float*)d_in[3];
    const float* conv_w0 = (const float*)d_in[4];
    const float* conv_b0 = (const float*)d_in[5];
    const float* conv_w1 = (const float*)d_in[6];
    const float* conv_b1 = (const float*)d_in[7];
    const float* proj_w  = (const float*)d_in[8];
    const float* proj_b  = (const float*)d_in[9];
    const float* norm2_w = (const float*)d_in[10];
    const float* norm2_b = (const float*)d_in[11];
    const float* fc1_w   = (const float*)d_in[12];
    const float* fc1_b   = (const float*)d_in[13];
    const float* fc2_w   = (const float*)d_in[14];
    const float* fc2_b   = (const float*)d_in[15];
    float* out = (float*)d_out;

    __nv_bfloat16 *p_img, *p_att, *p_y, *p_hid, *p_qkv;
    __nv_bfloat16 *p_wqkv, *p_wproj, *p_wfc1, *p_wfc2;
    float *p_x2;
    cudaGetSymbolAddress((void**)&p_img, g_img);
    cudaGetSymbolAddress((void**)&p_qkv, g_qkv);
    cudaGetSymbolAddress((void**)&p_att, g_att);
    cudaGetSymbolAddress((void**)&p_x2,  g_x2);
    cudaGetSymbolAddress((void**)&p_y,   g_y);
    cudaGetSymbolAddress((void**)&p_hid, g_hid);
    cudaGetSymbolAddress((void**)&p_wqkv,  g_wqkv);
    cudaGetSymbolAddress((void**)&p_wproj, g_wproj);
    cudaGetSymbolAddress((void**)&p_wfc1,  g_wfc1);
    cudaGetSymbolAddress((void**)&p_wfc2,  g_wfc2);

    dim3 lnBlock(32, 8);

    // 0. weights -> bf16
    convert_weights<<<768, 256>>>(qkv_w, proj_w, fc1_w, fc2_w);

    // 1. LN1 -> bf16
    ln_kernel<<<MROWS / 8, lnBlock>>>(x, norm1_w, norm1_b, p_img);

    // 2. QKV GEMM -> bf16
    hgemm_kernel<0><<<dim3(3, MROWS / 128), 256>>>(
        384, 128, p_img, p_wqkv, nullptr, nullptr, p_qkv);

    // 3. Tensor-core attention + LePE -> bf16
    attn_mma_kernel<<<512, 256>>>(p_qkv, conv_w0, conv_b0, conv_w1, conv_b1);

    // 4. proj + bias + residual(x) -> x2 (fp32)
    hgemm_kernel<3><<<dim3(1, MROWS / 128), 256>>>(
        128, 128, p_att, p_wproj, proj_b, x, p_x2);

    // 5. LN2 -> bf16
    ln_kernel<<<MROWS / 8, lnBlock>>>(p_x2, norm2_w, norm2_b, p_y);

    // 6. fc1 + bias + gelu -> bf16
    hgemm_kernel<2><<<dim3(4, MROWS / 128), 256>>>(
        512, 128, p_y, p_wfc1, fc1_b, nullptr, p_hid);

    // 7. fc2 + bias + residual(x2) -> out (fp32)
    hgemm_kernel<3><<<dim3(1, MROWS / 128), 256>>>(
        128, 512, p_hid, p_wfc2, fc2_b, p_x2, out);
}

// round 14
// speedup vs baseline: 7.1664x; 1.1945x over previous
#include <cuda_runtime.h>
#include <cuda_bf16.h>
#include <math.h>

// ---------------------------------------------------------------------------
// Problem constants
// ---------------------------------------------------------------------------
#define BB     4
#define TT     8
#define RESO   32
#define CC     128
#define LL     (TT * RESO * RESO)     // 8192
#define MROWS  (BB * LL)              // 32768
#define HID    (4 * CC)               // 512

// ---------------------------------------------------------------------------
// Device scratch
// ---------------------------------------------------------------------------
__device__ __nv_bfloat16 g_img[(size_t)MROWS * CC];       // LN1 output (bf16)
__device__ __nv_bfloat16 g_qkv[(size_t)MROWS * 3 * CC];   // qkv (bf16)
__device__ __nv_bfloat16 g_att[(size_t)MROWS * CC];       // attention output (bf16)
__device__ float         g_x2 [(size_t)MROWS * CC];       // x + proj(att)  (fp32)
__device__ __nv_bfloat16 g_y  [(size_t)MROWS * CC];       // LN2 output (bf16)
__device__ __nv_bfloat16 g_hid[(size_t)MROWS * HID];      // gelu(fc1) (bf16)

__device__ __nv_bfloat16 g_wqkv[384 * 128];
__device__ __nv_bfloat16 g_wproj[128 * 128];
__device__ __nv_bfloat16 g_wfc1[512 * 128];
__device__ __nv_bfloat16 g_wfc2[128 * 512];

// bit-cast helpers
__device__ __forceinline__ unsigned __bf2u(__nv_bfloat162 v)
{
    return *(unsigned*)&v;
}
__device__ __forceinline__ unsigned packbf(float lo, float hi)
{
    return __bf2u(__float22bfloat162_rn(make_float2(lo, hi)));
}
__device__ __forceinline__ float ex2f(float x)
{
    float r;
    asm("ex2.approx.f32 %0, %1;" : "=f"(r) : "f"(x));
    return r;
}

// ---------------------------------------------------------------------------
// Weight fp32 -> bf16 conversion
// ---------------------------------------------------------------------------
__global__ void convert_weights(const float* __restrict__ qkvw,
                                const float* __restrict__ projw,
                                const float* __restrict__ fc1w,
                                const float* __restrict__ fc2w)
{
    int i = blockIdx.x * 256 + threadIdx.x;
    if (i < 49152)       g_wqkv[i]           = __float2bfloat16(qkvw[i]);
    else if (i < 65536)  g_wproj[i - 49152]  = __float2bfloat16(projw[i - 49152]);
    else if (i < 131072) g_wfc1[i - 65536]   = __float2bfloat16(fc1w[i - 65536]);
    else if (i < 196608) g_wfc2[i - 131072]  = __float2bfloat16(fc2w[i - 131072]);
}

// ---------------------------------------------------------------------------
// LayerNorm: one warp per token, bf16 output
// ---------------------------------------------------------------------------
__global__ void ln_kernel(const float* __restrict__ x,
                          const float* __restrict__ w,
                          const float* __restrict__ b,
                          __nv_bfloat16* __restrict__ out)
{
    int row  = blockIdx.x * 8 + threadIdx.y;
    int lane = threadIdx.x;
    const float4* rp = (const float4*)(x + (size_t)row * CC);
    float4 v = rp[lane];
    float s  = v.x + v.y + v.z + v.w;
    float ss = v.x * v.x + v.y * v.y + v.z * v.z + v.w * v.w;
    #pragma unroll
    for (int o = 16; o > 0; o >>= 1) {
        s  += __shfl_xor_sync(0xffffffffu, s,  o);
        ss += __shfl_xor_sync(0xffffffffu, ss, o);
    }
    float mean = s * (1.0f / CC);
    float var  = ss * (1.0f / CC) - mean * mean;
    float rstd = rsqrtf(var + 1e-5f);
    float4 wv = ((const float4*)w)[lane];
    float4 bv = ((const float4*)b)[lane];
    uint2 u;
    u.x = packbf((v.x - mean) * rstd * wv.x + bv.x, (v.y - mean) * rstd * wv.y + bv.y);
    u.y = packbf((v.z - mean) * rstd * wv.z + bv.z, (v.w - mean) * rstd * wv.w + bv.w);
    ((uint2*)(out + (size_t)row * CC))[lane] = u;
}

// ---------------------------------------------------------------------------
// mma / ldmatrix helpers
// ---------------------------------------------------------------------------
__device__ __forceinline__ float gelu_exact(float v)
{
    return 0.5f * v * (1.0f + erff(v * 0.70710678118654752f));
}

__device__ __forceinline__ void ldsm4(unsigned& r0, unsigned& r1, unsigned& r2,
                                      unsigned& r3, unsigned addr)
{
    asm volatile("ldmatrix.sync.aligned.m8n8.x4.shared.b16 {%0,%1,%2,%3}, [%4];"
                 : "=r"(r0), "=r"(r1), "=r"(r2), "=r"(r3) : "r"(addr));
}

__device__ __forceinline__ void mma16816(float* c, const unsigned* a,
                                         unsigned b0, unsigned b1)
{
    asm volatile(
        "mma.sync.aligned.m16n8k16.row.col.f32.bf16.bf16.f32 "
        "{%0,%1,%2,%3}, {%4,%5,%6,%7}, {%8,%9}, {%0,%1,%2,%3};"
        : "+f"(c[0]), "+f"(c[1]), "+f"(c[2]), "+f"(c[3])
        : "r"(a[0]), "r"(a[1]), "r"(a[2]), "r"(a[3]), "r"(b0), "r"(b1));
}

// ---------------------------------------------------------------------------
// bf16 tensor-core GEMM
// ---------------------------------------------------------------------------
#define PADK 40

template <int EPI>
__global__ void __launch_bounds__(256)
hgemm_kernel(int Nd, int Kd,
             const __nv_bfloat16* __restrict__ A,
             const __nv_bfloat16* __restrict__ Bm,
             const float* __restrict__ bias,
             const float* __restrict__ resid,
             void* __restrict__ CoutV)
{
    __shared__ __nv_bfloat16 As[2][128 * PADK];
    __shared__ __nv_bfloat16 Bs[2][128 * PADK];

    int tid  = threadIdx.x;
    int lane = tid & 31;
    int wid  = tid >> 5;
    int wm   = wid >> 2;
    int wn   = wid & 3;
    int m0   = blockIdx.y * 128;
    int n0   = blockIdx.x * 128;

    int ldRow0 = (tid + 0)   >> 2, ldCol0 = ((tid + 0)   & 3) * 8;
    int ldRow1 = (tid + 256) >> 2, ldCol1 = ((tid + 256) & 3) * 8;

    const __nv_bfloat16* Ag0 = A  + (size_t)(m0 + ldRow0) * Kd + ldCol0;
    const __nv_bfloat16* Ag1 = A  + (size_t)(m0 + ldRow1) * Kd + ldCol1;
    const __nv_bfloat16* Bg0 = Bm + (size_t)(n0 + ldRow0) * Kd + ldCol0;
    const __nv_bfloat16* Bg1 = Bm + (size_t)(n0 + ldRow1) * Kd + ldCol1;

    unsigned aOff = ((wm * 64 + (lane & 15)) * PADK + (lane >> 4) * 8) * 2;
    int g = lane >> 3;
    unsigned bOff = ((((g & 1) * 8 + (lane & 7)) + wn * 32) * PADK + (g >> 1) * 8) * 2;

    float acc[4][4][4];
    #pragma unroll
    for (int i = 0; i < 4; i++)
        #pragma unroll
        for (int j = 0; j < 4; j++)
            #pragma unroll
            for (int r = 0; r < 4; r++) acc[i][j][r] = 0.0f;

    int KT = Kd >> 5;

    {
        uint4 a0 = *(const uint4*)Ag0, a1 = *(const uint4*)Ag1;
        uint4 b0 = *(const uint4*)Bg0, b1 = *(const uint4*)Bg1;
        *(uint4*)(As[0] + ldRow0 * PADK + ldCol0) = a0;
        *(uint4*)(As[0] + ldRow1 * PADK + ldCol1) = a1;
        *(uint4*)(Bs[0] + ldRow0 * PADK + ldCol0) = b0;
        *(uint4*)(Bs[0] + ldRow1 * PADK + ldCol1) = b1;
    }
    __syncthreads();

    int buf = 0;
    for (int t = 0; t < KT; t++) {
        uint4 pa0, pa1, pb0, pb1;
        if (t + 1 < KT) {
            int ko = (t + 1) << 5;
            pa0 = *(const uint4*)(Ag0 + ko);
            pa1 = *(const uint4*)(Ag1 + ko);
            pb0 = *(const uint4*)(Bg0 + ko);
            pb1 = *(const uint4*)(Bg1 + ko);
        }

        unsigned aB = (unsigned)__cvta_generic_to_shared(&As[buf][0]) + aOff;
        unsigned bB = (unsigned)__cvta_generic_to_shared(&Bs[buf][0]) + bOff;

        #pragma unroll
        for (int ks = 0; ks < 2; ks++) {
            unsigned af[4][4];
            #pragma unroll
            for (int mf = 0; mf < 4; mf++)
                ldsm4(af[mf][0], af[mf][1], af[mf][2], af[mf][3],
                      aB + mf * 16 * PADK * 2 + ks * 32);
            unsigned bfr[2][4];
            #pragma unroll
            for (int np = 0; np < 2; np++)
                ldsm4(bfr[np][0], bfr[np][1], bfr[np][2], bfr[np][3],
                      bB + np * 16 * PADK * 2 + ks * 32);
            #pragma unroll
            for (int mf = 0; mf < 4; mf++) {
                #pragma unroll
                for (int np = 0; np < 2; np++) {
                    mma16816(acc[mf][np * 2 + 0], af[mf], bfr[np][0], bfr[np][2]);
                    mma16816(acc[mf][np * 2 + 1], af[mf], bfr[np][1], bfr[np][3]);
                }
            }
        }

        if (t + 1 < KT) {
            int nb = buf ^ 1;
            *(uint4*)(As[nb] + ldRow0 * PADK + ldCol0) = pa0;
            *(uint4*)(As[nb] + ldRow1 * PADK + ldCol1) = pa1;
            *(uint4*)(Bs[nb] + ldRow0 * PADK + ldCol0) = pb0;
            *(uint4*)(Bs[nb] + ldRow1 * PADK + ldCol1) = pb1;
        }
        __syncthreads();
        buf ^= 1;
    }

    int lr = lane >> 2;
    int lc = (lane & 3) * 2;
    #pragma unroll
    for (int mf = 0; mf < 4; mf++) {
        #pragma unroll
        for (int nf = 0; nf < 4; nf++) {
            int row = m0 + wm * 64 + mf * 16 + lr;
            int col = n0 + wn * 32 + nf * 8 + lc;
            float* c = acc[mf][nf];
            #pragma unroll
            for (int half = 0; half < 2; half++) {
                int r  = row + half * 8;
                float v0 = c[half * 2 + 0];
                float v1 = c[half * 2 + 1];
                size_t off = (size_t)r * Nd + col;
                if (EPI == 0) {
                    *(unsigned*)((__nv_bfloat16*)CoutV + off) = packbf(v0, v1);
                } else if (EPI == 2) {
                    v0 = gelu_exact(v0 + bias[col]);
                    v1 = gelu_exact(v1 + bias[col + 1]);
                    *(unsigned*)((__nv_bfloat16*)CoutV + off) = packbf(v0, v1);
                } else { // EPI == 3
                    v0 += bias[col]     + resid[off];
                    v1 += bias[col + 1] + resid[off + 1];
                    ((float2*)((float*)CoutV + off))[0] = make_float2(v0, v1);
                }
            }
        }
    }
}

// ---------------------------------------------------------------------------
// Tensor-core windowed attention + fused LePE.
// One CTA per (branch, window, head, half): 256 q x 512 k, hd=16, bf16 mma.
// 8 warps; warp w owns q rows [half*256 + w*32, +32).
// Row sums via ones-column mma; exp via raw ex2 (log2e folded into q scale).
// K smem [512][24] bf16; V smem transposed [16][520] bf16.
// ---------------------------------------------------------------------------
__global__ void __launch_bounds__(256, 2)
attn_mma_kernel(const __nv_bfloat16* __restrict__ qkv,
                const float* __restrict__ conv_w0, const float* __restrict__ conv_b0,
                const float* __restrict__ conv_w1, const float* __restrict__ conv_b1)
{
    __shared__ __nv_bfloat16 Ks[512 * 24];
    __shared__ __nv_bfloat16 Vt[16 * 520];
    __shared__ float cw[16 * 27];
    __shared__ float cb[16];

    int cta    = blockIdx.x;
    int branch = cta >> 9;
    int rem    = cta & 511;
    int win    = rem >> 3;
    int head   = (rem >> 1) & 3;
    int half   = rem & 1;

    int Hsp   = branch ? 4 : 32;
    int Wsp   = branch ? 32 : 4;
    int lw    = branch ? 5 : 2;
    int wmask = Wsp - 1;
    int nWw   = branch ? 1 : 8;

    int bidx = win >> 4;
    int wrem = win & 15;
    int wt   = wrem >> 3;
    int wsp  = wrem & 7;
    int wh   = wsp / nWw;
    int ww   = wsp % nWw;

    int choff = branch * 64 + head * 16;
    int tid  = threadIdx.x;
    int lane = tid & 31;
    int warp = tid >> 5;

    #define ROW_OF(p, itv, ihv, iwv, lrowv)                              \
        int itv = (p) >> 7;                                              \
        int ihv = ((p) & 127) >> lw;                                     \
        int iwv = (p) & wmask;                                           \
        int lrowv = bidx * LL + ((wt * 4 + itv) << 10)                   \
                  + ((wh * Hsp + ihv) << 5) + (ww * Wsp + iwv);

    // ---- stage K (row-major, pad 24) and V (transposed [16][520]) ----
    for (int p = tid; p < 512; p += 256) {
        ROW_OF(p, a_, b_, c_, lrow); (void)a_; (void)b_; (void)c_;
        const uint4* kp = (const uint4*)(qkv + (size_t)lrow * 384 + 128 + choff);
        uint4 k0 = kp[0], k1 = kp[1];
        *(uint4*)(Ks + p * 24 + 0) = k0;
        *(uint4*)(Ks + p * 24 + 8) = k1;
        const uint4* vp = (const uint4*)(qkv + (size_t)lrow * 384 + 256 + choff);
        uint4 v0 = vp[0], v1 = vp[1];
        __nv_bfloat16 vtmp[16];
        *(uint4*)(vtmp + 0) = v0;
        *(uint4*)(vtmp + 8) = v1;
        #pragma unroll
        for (int d = 0; d < 16; d++) Vt[d * 520 + p] = vtmp[d];
    }
    const float* cwp = branch ? conv_w1 : conv_w0;
    const float* cbp = branch ? conv_b1 : conv_b0;
    for (int i = tid; i < 16 * 27; i += 256) cw[i] = cwp[head * 432 + i];
    if (tid < 16) cb[tid] = cbp[head * 16 + tid];

    // ---- Q a-frags: scale = 0.25 * log2(e) so scores feed ex2 directly ----
    int qr = lane >> 2;
    int qc = (lane & 3) * 2;
    __nv_bfloat162 qscale = __float2bfloat162_rn(0.25f * 1.4426950408889634f);
    unsigned qa[2][4];
    int qbase = half * 256 + warp * 32;
    #pragma unroll
    for (int mt = 0; mt < 2; mt++) {
        int pr0 = qbase + mt * 16 + qr;
        int pr1 = pr0 + 8;
        ROW_OF(pr0, a0_, b0_, c0_, lrow0); (void)a0_; (void)b0_; (void)c0_;
        ROW_OF(pr1, a1_, b1_, c1_, lrow1); (void)a1_; (void)b1_; (void)c1_;
        const __nv_bfloat16* q0p = qkv + (size_t)lrow0 * 384 + choff;
        const __nv_bfloat16* q1p = qkv + (size_t)lrow1 * 384 + choff;
        __nv_bfloat162 t;
        t = __hmul2(*(const __nv_bfloat162*)(q0p + qc),     qscale); qa[mt][0] = __bf2u(t);
        t = __hmul2(*(const __nv_bfloat162*)(q1p + qc),     qscale); qa[mt][1] = __bf2u(t);
        t = __hmul2(*(const __nv_bfloat162*)(q0p + qc + 8), qscale); qa[mt][2] = __bf2u(t);
        t = __hmul2(*(const __nv_bfloat162*)(q1p + qc + 8), qscale); qa[mt][3] = __bf2u(t);
    }
    __syncthreads();

    // ---- streaming attention over 16 k-tiles of 32 keys ----
    float oAcc[2][2][4];
    float sAcc[2][4];          // ones-column row-sum accumulators
    #pragma unroll
    for (int mt = 0; mt < 2; mt++) {
        #pragma unroll
        for (int nf = 0; nf < 2; nf++)
            #pragma unroll
            for (int r = 0; r < 4; r++) oAcc[mt][nf][r] = 0.0f;
        #pragma unroll
        for (int r = 0; r < 4; r++) sAcc[mt][r] = 0.0f;
    }

    // ones b-frag: column 0 of an 8-col B tile = 1, rest 0
    unsigned ones = (lane < 4) ? packbf(1.0f, 1.0f) : 0u;

    int g = lane >> 3;
    unsigned ksBase = (unsigned)__cvta_generic_to_shared(Ks);
    unsigned vtBase = (unsigned)__cvta_generic_to_shared(Vt);
    unsigned kRowOff = ((g & 1) * 8 + (lane & 7)) * 24 * 2 + (g >> 1) * 8 * 2;
    unsigned vRowOff = ((g & 1) * 8 + (lane & 7)) * 520 * 2 + (g >> 1) * 8 * 2;

    for (int kt = 0; kt < 16; kt++) {
        unsigned kb[4][2];
        {
            unsigned u0, u1, u2, u3;
            unsigned base = ksBase + kt * 32 * 24 * 2 + kRowOff;
            ldsm4(u0, u1, u2, u3, base);
            kb[0][0] = u0; kb[0][1] = u2; kb[1][0] = u1; kb[1][1] = u3;
            ldsm4(u0, u1, u2, u3, base + 16 * 24 * 2);
            kb[2][0] = u0; kb[2][1] = u2; kb[3][0] = u1; kb[3][1] = u3;
        }
        unsigned vb[4][2];
        {
            unsigned u0, u1, u2, u3;
            unsigned base = vtBase + kt * 32 * 2 + vRowOff;
            ldsm4(u0, u1, u2, u3, base);
            vb[0][0] = u0; vb[0][1] = u2; vb[1][0] = u1; vb[1][1] = u3;
            ldsm4(u0, u1, u2, u3, base + 16 * 2);
            vb[2][0] = u0; vb[2][1] = u2; vb[3][0] = u1; vb[3][1] = u3;
        }

        #pragma unroll
        for (int mt = 0; mt < 2; mt++) {
            float s[4][4];
            #pragma unroll
            for (int nf = 0; nf < 4; nf++) {
                s[nf][0] = 0.0f; s[nf][1] = 0.0f; s[nf][2] = 0.0f; s[nf][3] = 0.0f;
                mma16816(s[nf], qa[mt], kb[nf][0], kb[nf][1]);
            }
            #pragma unroll
            for (int nf = 0; nf < 4; nf++) {
                #pragma unroll
                for (int e = 0; e < 4; e++)
                    s[nf][e] = ex2f(fminf(s[nf][e], 43.0f));
            }
            unsigned pa0[4], pa1[4];
            pa0[0] = packbf(s[0][0], s[0][1]);
            pa0[1] = packbf(s[0][2], s[0][3]);
            pa0[2] = packbf(s[1][0], s[1][1]);
            pa0[3] = packbf(s[1][2], s[1][3]);
            pa1[0] = packbf(s[2][0], s[2][1]);
            pa1[1] = packbf(s[2][2], s[2][3]);
            pa1[2] = packbf(s[3][0], s[3][1]);
            pa1[3] = packbf(s[3][2], s[3][3]);
            // PV + ones-column row sums
            mma16816(oAcc[mt][0], pa0, vb[0][0], vb[0][1]);
            mma16816(oAcc[mt][1], pa0, vb[1][0], vb[1][1]);
            mma16816(sAcc[mt],    pa0, ones,     ones);
            mma16816(oAcc[mt][0], pa1, vb[2][0], vb[2][1]);
            mma16816(oAcc[mt][1], pa1, vb[3][0], vb[3][1]);
            mma16816(sAcc[mt],    pa1, ones,     ones);
        }
    }

    // ---- broadcast row sums from quad lane 0 (col 0 owners) ----
    float inv[2][2];
    #pragma unroll
    for (int mt = 0; mt < 2; mt++) {
        float s0 = __shfl_sync(0xffffffffu, sAcc[mt][0], lane & 28);
        float s1 = __shfl_sync(0xffffffffu, sAcc[mt][2], lane & 28);
        inv[mt][0] = 1.0f / s0;
        inv[mt][1] = 1.0f / s1;
    }

    // ---- epilogue: 1/sum, conv bias, fused LePE gather, store ----
    #pragma unroll
    for (int mt = 0; mt < 2; mt++) {
        #pragma unroll
        for (int h = 0; h < 2; h++) {
            int p = qbase + mt * 16 + qr + h * 8;
            ROW_OF(p, it, ih, iw, lrow);
            float iv = inv[mt][h];
            int d0 = qc, d2 = qc + 8;
            float a0 = oAcc[mt][0][h * 2 + 0] * iv + cb[d0];
            float a1 = oAcc[mt][0][h * 2 + 1] * iv + cb[d0 + 1];
            float a2 = oAcc[mt][1][h * 2 + 0] * iv + cb[d2];
            float a3 = oAcc[mt][1][h * 2 + 1] * iv + cb[d2 + 1];

            #pragma unroll
            for (int dz = 0; dz < 3; dz++) {
                int z = it + dz - 1;
                if (z < 0 || z >= 4) continue;
                #pragma unroll
                for (int dy = 0; dy < 3; dy++) {
                    int y = ih + dy - 1;
                    if (y < 0 || y >= Hsp) continue;
                    #pragma unroll
                    for (int dx = 0; dx < 3; dx++) {
                        int x = iw + dx - 1;
                        if (x < 0 || x >= Wsp) continue;
                        int widx = dz * 9 + dy * 3 + dx;
                        int pos = (z << 7) + (y << lw) + x;
                        a0 += cw[d0 * 27 + widx]       * __bfloat162float(Vt[d0 * 520 + pos]);
                        a1 += cw[(d0 + 1) * 27 + widx] * __bfloat162float(Vt[(d0 + 1) * 520 + pos]);
                        a2 += cw[d2 * 27 + widx]       * __bfloat162float(Vt[d2 * 520 + pos]);
                        a3 += cw[(d2 + 1) * 27 + widx] * __bfloat162float(Vt[(d2 + 1) * 520 + pos]);
                    }
                }
            }
            __nv_bfloat16* op = g_att + (size_t)lrow * CC + choff;
            *(unsigned*)(op + d0) = packbf(a0, a1);
            *(unsigned*)(op + d2) = packbf(a2, a3);
        }
    }
    #undef ROW_OF
}

// ---------------------------------------------------------------------------
// Launch
// ---------------------------------------------------------------------------
extern "C" void kernel_launch(void* const* d_in, const int* in_sizes, int n_in,
                              void* d_out, int out_size)
{
    const float* x       = (const float*)d_in[0];
    const float* norm1_w = (const float*)d_in[1];
    const float* norm1_b = (const float*)d_in[2];
    const float* qkv_w   = (const float*)d_in[3];
    const float* conv_w0 = (const float*)d_in[4];
    const float* conv_b0 = (const float*)d_in[5];
    const float* conv_w1 = (const float*)d_in[6];
    const float* conv_b1 = (const float*)d_in[7];
    const float* proj_w  = (const float*)d_in[8];
    const float* proj_b  = (const float*)d_in[9];
    const float* norm2_w = (const float*)d_in[10];
    const float* norm2_b = (const float*)d_in[11];
    const float* fc1_w   = (const float*)d_in[12];
    const float* fc1_b   = (const float*)d_in[13];
    const float* fc2_w   = (const float*)d_in[14];
    const float* fc2_b   = (const float*)d_in[15];
    float* out = (float*)d_out;

    __nv_bfloat16 *p_img, *p_att, *p_y, *p_hid, *p_qkv;
    __nv_bfloat16 *p_wqkv, *p_wproj, *p_wfc1, *p_wfc2;
    float *p_x2;
    cudaGetSymbolAddress((void**)&p_img, g_img);
    cudaGetSymbolAddress((void**)&p_qkv, g_qkv);
    cudaGetSymbolAddress((void**)&p_att, g_att);
    cudaGetSymbolAddress((void**)&p_x2,  g_x2);
    cudaGetSymbolAddress((void**)&p_y,   g_y);
    cudaGetSymbolAddress((void**)&p_hid, g_hid);
    cudaGetSymbolAddress((void**)&p_wqkv,  g_wqkv);
    cudaGetSymbolAddress((void**)&p_wproj, g_wproj);
    cudaGetSymbolAddress((void**)&p_wfc1,  g_wfc1);
    cudaGetSymbolAddress((void**)&p_wfc2,  g_wfc2);

    dim3 lnBlock(32, 8);

    // 0. weights -> bf16
    convert_weights<<<768, 256>>>(qkv_w, proj_w, fc1_w, fc2_w);

    // 1. LN1 -> bf16
    ln_kernel<<<MROWS / 8, lnBlock>>>(x, norm1_w, norm1_b, p_img);

    // 2. QKV GEMM -> bf16
    hgemm_kernel<0><<<dim3(3, MROWS / 128), 256>>>(
        384, 128, p_img, p_wqkv, nullptr, nullptr, p_qkv);

    // 3. Tensor-core attention + LePE -> bf16  (2 CTAs per window-head)
    attn_mma_kernel<<<1024, 256>>>(p_qkv, conv_w0, conv_b0, conv_w1, conv_b1);

    // 4. proj + bias + residual(x) -> x2 (fp32)
    hgemm_kernel<3><<<dim3(1, MROWS / 128), 256>>>(
        128, 128, p_att, p_wproj, proj_b, x, p_x2);

    // 5. LN2 -> bf16
    ln_kernel<<<MROWS / 8, lnBlock>>>(p_x2, norm2_w, norm2_b, p_y);

    // 6. fc1 + bias + gelu -> bf16
    hgemm_kernel<2><<<dim3(4, MROWS / 128), 256>>>(
        512, 128, p_y, p_wfc1, fc1_b, nullptr, p_hid);

    // 7. fc2 + bias + residual(x2) -> out (fp32)
    hgemm_kernel<3><<<dim3(1, MROWS / 128), 256>>>(
        128, 512, p_hid, p_wfc2, fc2_b, p_x2, out);
}

// round 17
// speedup vs baseline: 7.3200x; 1.0214x over previous
#include <cuda_runtime.h>
#include <cuda_bf16.h>
#include <math.h>

// ---------------------------------------------------------------------------
// Problem constants
// ---------------------------------------------------------------------------
#define BB     4
#define TT     8
#define RESO   32
#define CC     128
#define LL     (TT * RESO * RESO)     // 8192
#define MROWS  (BB * LL)              // 32768
#define HID    (4 * CC)               // 512

// ---------------------------------------------------------------------------
// Device scratch
// ---------------------------------------------------------------------------
__device__ __nv_bfloat16 g_img[(size_t)MROWS * CC];       // LN1 output (bf16)
__device__ __nv_bfloat16 g_qkv[(size_t)MROWS * 3 * CC];   // qkv (bf16)
__device__ __nv_bfloat16 g_att[(size_t)MROWS * CC];       // attention output (bf16)
__device__ float         g_x2 [(size_t)MROWS * CC];       // x + proj(att)  (fp32)
__device__ __nv_bfloat16 g_y  [(size_t)MROWS * CC];       // LN2 output (bf16)
__device__ __nv_bfloat16 g_hid[(size_t)MROWS * HID];      // gelu(fc1) (bf16)

__device__ __nv_bfloat16 g_wqkv[384 * 128];
__device__ __nv_bfloat16 g_wproj[128 * 128];
__device__ __nv_bfloat16 g_wfc1[512 * 128];
__device__ __nv_bfloat16 g_wfc2[128 * 512];

// bit-cast helpers
__device__ __forceinline__ unsigned __bf2u(__nv_bfloat162 v)
{
    return *(unsigned*)&v;
}
__device__ __forceinline__ unsigned packbf(float lo, float hi)
{
    return __bf2u(__float22bfloat162_rn(make_float2(lo, hi)));
}
__device__ __forceinline__ float ex2f(float x)
{
    float r;
    asm("ex2.approx.f32 %0, %1;" : "=f"(r) : "f"(x));
    return r;
}

// ---------------------------------------------------------------------------
// Weight fp32 -> bf16 conversion
// ---------------------------------------------------------------------------
__global__ void convert_weights(const float* __restrict__ qkvw,
                                const float* __restrict__ projw,
                                const float* __restrict__ fc1w,
                                const float* __restrict__ fc2w)
{
    int i = blockIdx.x * 256 + threadIdx.x;
    if (i < 49152)       g_wqkv[i]           = __float2bfloat16(qkvw[i]);
    else if (i < 65536)  g_wproj[i - 49152]  = __float2bfloat16(projw[i - 49152]);
    else if (i < 131072) g_wfc1[i - 65536]   = __float2bfloat16(fc1w[i - 65536]);
    else if (i < 196608) g_wfc2[i - 131072]  = __float2bfloat16(fc2w[i - 131072]);
}

// ---------------------------------------------------------------------------
// LayerNorm: one warp per token, bf16 output
// ---------------------------------------------------------------------------
__global__ void ln_kernel(const float* __restrict__ x,
                          const float* __restrict__ w,
                          const float* __restrict__ b,
                          __nv_bfloat16* __restrict__ out)
{
    int row  = blockIdx.x * 8 + threadIdx.y;
    int lane = threadIdx.x;
    const float4* rp = (const float4*)(x + (size_t)row * CC);
    float4 v = rp[lane];
    float s  = v.x + v.y + v.z + v.w;
    float ss = v.x * v.x + v.y * v.y + v.z * v.z + v.w * v.w;
    #pragma unroll
    for (int o = 16; o > 0; o >>= 1) {
        s  += __shfl_xor_sync(0xffffffffu, s,  o);
        ss += __shfl_xor_sync(0xffffffffu, ss, o);
    }
    float mean = s * (1.0f / CC);
    float var  = ss * (1.0f / CC) - mean * mean;
    float rstd = rsqrtf(var + 1e-5f);
    float4 wv = ((const float4*)w)[lane];
    float4 bv = ((const float4*)b)[lane];
    uint2 u;
    u.x = packbf((v.x - mean) * rstd * wv.x + bv.x, (v.y - mean) * rstd * wv.y + bv.y);
    u.y = packbf((v.z - mean) * rstd * wv.z + bv.z, (v.w - mean) * rstd * wv.w + bv.w);
    ((uint2*)(out + (size_t)row * CC))[lane] = u;
}

// ---------------------------------------------------------------------------
// mma / ldmatrix helpers
// ---------------------------------------------------------------------------
__device__ __forceinline__ float gelu_exact(float v)
{
    return 0.5f * v * (1.0f + erff(v * 0.70710678118654752f));
}

__device__ __forceinline__ void ldsm4(unsigned& r0, unsigned& r1, unsigned& r2,
                                      unsigned& r3, unsigned addr)
{
    asm volatile("ldmatrix.sync.aligned.m8n8.x4.shared.b16 {%0,%1,%2,%3}, [%4];"
                 : "=r"(r0), "=r"(r1), "=r"(r2), "=r"(r3) : "r"(addr));
}

__device__ __forceinline__ void mma16816(float* c, const unsigned* a,
                                         unsigned b0, unsigned b1)
{
    asm volatile(
        "mma.sync.aligned.m16n8k16.row.col.f32.bf16.bf16.f32 "
        "{%0,%1,%2,%3}, {%4,%5,%6,%7}, {%8,%9}, {%0,%1,%2,%3};"
        : "+f"(c[0]), "+f"(c[1]), "+f"(c[2]), "+f"(c[3])
        : "r"(a[0]), "r"(a[1]), "r"(a[2]), "r"(a[3]), "r"(b0), "r"(b1));
}

// ---------------------------------------------------------------------------
// bf16 tensor-core GEMM
// EPI: 0 -> bf16 out; 2 -> bias+gelu bf16 out; 3 -> bias+resid fp32 out;
//      4 -> bias+resid fp32 out + fused LayerNorm bf16 out (requires Nd==128,
//           gridDim.x==1 so each CTA owns complete rows)
// ---------------------------------------------------------------------------
#define PADK 40

template <int EPI>
__global__ void __launch_bounds__(256)
hgemm_kernel(int Nd, int Kd,
             const __nv_bfloat16* __restrict__ A,
             const __nv_bfloat16* __restrict__ Bm,
             const float* __restrict__ bias,
             const float* __restrict__ resid,
             void* __restrict__ CoutV,
             const float* __restrict__ lnw,
             const float* __restrict__ lnb,
             __nv_bfloat16* __restrict__ Cout2)
{
    __shared__ __nv_bfloat16 As[2][128 * PADK];
    __shared__ __nv_bfloat16 Bs[2][128 * PADK];
    __shared__ float2 red[128][4];          // EPI==4 row partials

    int tid  = threadIdx.x;
    int lane = tid & 31;
    int wid  = tid >> 5;
    int wm   = wid >> 2;
    int wn   = wid & 3;
    int m0   = blockIdx.y * 128;
    int n0   = blockIdx.x * 128;

    int ldRow0 = (tid + 0)   >> 2, ldCol0 = ((tid + 0)   & 3) * 8;
    int ldRow1 = (tid + 256) >> 2, ldCol1 = ((tid + 256) & 3) * 8;

    const __nv_bfloat16* Ag0 = A  + (size_t)(m0 + ldRow0) * Kd + ldCol0;
    const __nv_bfloat16* Ag1 = A  + (size_t)(m0 + ldRow1) * Kd + ldCol1;
    const __nv_bfloat16* Bg0 = Bm + (size_t)(n0 + ldRow0) * Kd + ldCol0;
    const __nv_bfloat16* Bg1 = Bm + (size_t)(n0 + ldRow1) * Kd + ldCol1;

    unsigned aOff = ((wm * 64 + (lane & 15)) * PADK + (lane >> 4) * 8) * 2;
    int g = lane >> 3;
    unsigned bOff = ((((g & 1) * 8 + (lane & 7)) + wn * 32) * PADK + (g >> 1) * 8) * 2;

    float acc[4][4][4];
    #pragma unroll
    for (int i = 0; i < 4; i++)
        #pragma unroll
        for (int j = 0; j < 4; j++)
            #pragma unroll
            for (int r = 0; r < 4; r++) acc[i][j][r] = 0.0f;

    int KT = Kd >> 5;

    {
        uint4 a0 = *(const uint4*)Ag0, a1 = *(const uint4*)Ag1;
        uint4 b0 = *(const uint4*)Bg0, b1 = *(const uint4*)Bg1;
        *(uint4*)(As[0] + ldRow0 * PADK + ldCol0) = a0;
        *(uint4*)(As[0] + ldRow1 * PADK + ldCol1) = a1;
        *(uint4*)(Bs[0] + ldRow0 * PADK + ldCol0) = b0;
        *(uint4*)(Bs[0] + ldRow1 * PADK + ldCol1) = b1;
    }
    __syncthreads();

    int buf = 0;
    for (int t = 0; t < KT; t++) {
        uint4 pa0, pa1, pb0, pb1;
        if (t + 1 < KT) {
            int ko = (t + 1) << 5;
            pa0 = *(const uint4*)(Ag0 + ko);
            pa1 = *(const uint4*)(Ag1 + ko);
            pb0 = *(const uint4*)(Bg0 + ko);
            pb1 = *(const uint4*)(Bg1 + ko);
        }

        unsigned aB = (unsigned)__cvta_generic_to_shared(&As[buf][0]) + aOff;
        unsigned bB = (unsigned)__cvta_generic_to_shared(&Bs[buf][0]) + bOff;

        #pragma unroll
        for (int ks = 0; ks < 2; ks++) {
            unsigned af[4][4];
            #pragma unroll
            for (int mf = 0; mf < 4; mf++)
                ldsm4(af[mf][0], af[mf][1], af[mf][2], af[mf][3],
                      aB + mf * 16 * PADK * 2 + ks * 32);
            unsigned bfr[2][4];
            #pragma unroll
            for (int np = 0; np < 2; np++)
                ldsm4(bfr[np][0], bfr[np][1], bfr[np][2], bfr[np][3],
                      bB + np * 16 * PADK * 2 + ks * 32);
            #pragma unroll
            for (int mf = 0; mf < 4; mf++) {
                #pragma unroll
                for (int np = 0; np < 2; np++) {
                    mma16816(acc[mf][np * 2 + 0], af[mf], bfr[np][0], bfr[np][2]);
                    mma16816(acc[mf][np * 2 + 1], af[mf], bfr[np][1], bfr[np][3]);
                }
            }
        }

        if (t + 1 < KT) {
            int nb = buf ^ 1;
            *(uint4*)(As[nb] + ldRow0 * PADK + ldCol0) = pa0;
            *(uint4*)(As[nb] + ldRow1 * PADK + ldCol1) = pa1;
            *(uint4*)(Bs[nb] + ldRow0 * PADK + ldCol0) = pb0;
            *(uint4*)(Bs[nb] + ldRow1 * PADK + ldCol1) = pb1;
        }
        __syncthreads();
        buf ^= 1;
    }

    int lr = lane >> 2;
    int lc = (lane & 3) * 2;

    if (EPI == 4) {
        // ---- pass A: bias + residual into acc; per-row partial sums ----
        float psum[4][2], psq[4][2];
        #pragma unroll
        for (int mf = 0; mf < 4; mf++) {
            #pragma unroll
            for (int half = 0; half < 2; half++) { psum[mf][half] = 0.0f; psq[mf][half] = 0.0f; }
            #pragma unroll
            for (int nf = 0; nf < 4; nf++) {
                int col = wn * 32 + nf * 8 + lc;
                #pragma unroll
                for (int half = 0; half < 2; half++) {
                    int r = m0 + wm * 64 + mf * 16 + half * 8 + lr;
                    size_t off = (size_t)r * 128 + col;
                    float v0 = acc[mf][nf][half * 2 + 0] + bias[col]     + resid[off];
                    float v1 = acc[mf][nf][half * 2 + 1] + bias[col + 1] + resid[off + 1];
                    acc[mf][nf][half * 2 + 0] = v0;
                    acc[mf][nf][half * 2 + 1] = v1;
                    psum[mf][half] += v0 + v1;
                    psq[mf][half]  += v0 * v0 + v1 * v1;
                }
            }
        }
        // quad reduce (lanes differing in bits 0,1 share the row)
        #pragma unroll
        for (int mf = 0; mf < 4; mf++)
            #pragma unroll
            for (int half = 0; half < 2; half++) {
                float s = psum[mf][half], q = psq[mf][half];
                s += __shfl_xor_sync(0xffffffffu, s, 1);
                q += __shfl_xor_sync(0xffffffffu, q, 1);
                s += __shfl_xor_sync(0xffffffffu, s, 2);
                q += __shfl_xor_sync(0xffffffffu, q, 2);
                if ((lane & 3) == 0) {
                    int rowLocal = wm * 64 + mf * 16 + half * 8 + lr;
                    red[rowLocal][wn] = make_float2(s, q);
                }
            }
        __syncthreads();
        // ---- pass B: finalize stats, write x2 fp32 + LN bf16 ----
        #pragma unroll
        for (int mf = 0; mf < 4; mf++) {
            #pragma unroll
            for (int half = 0; half < 2; half++) {
                int rowLocal = wm * 64 + mf * 16 + half * 8 + lr;
                float2 p0 = red[rowLocal][0], p1 = red[rowLocal][1];
                float2 p2 = red[rowLocal][2], p3 = red[rowLocal][3];
                float s = p0.x + p1.x + p2.x + p3.x;
                float q = p0.y + p1.y + p2.y + p3.y;
                float mean = s * (1.0f / 128.0f);
                float var  = q * (1.0f / 128.0f) - mean * mean;
                float rstd = rsqrtf(var + 1e-5f);
                int r = m0 + rowLocal;
                #pragma unroll
                for (int nf = 0; nf < 4; nf++) {
                    int col = wn * 32 + nf * 8 + lc;
                    size_t off = (size_t)r * 128 + col;
                    float v0 = acc[mf][nf][half * 2 + 0];
                    float v1 = acc[mf][nf][half * 2 + 1];
                    ((float2*)((float*)CoutV + off))[0] = make_float2(v0, v1);
                    float y0 = (v0 - mean) * rstd * lnw[col]     + lnb[col];
                    float y1 = (v1 - mean) * rstd * lnw[col + 1] + lnb[col + 1];
                    *(unsigned*)(Cout2 + off) = packbf(y0, y1);
                }
            }
        }
        return;
    }

    #pragma unroll
    for (int mf = 0; mf < 4; mf++) {
        #pragma unroll
        for (int nf = 0; nf < 4; nf++) {
            int row = m0 + wm * 64 + mf * 16 + lr;
            int col = n0 + wn * 32 + nf * 8 + lc;
            float* c = acc[mf][nf];
            #pragma unroll
            for (int half = 0; half < 2; half++) {
                int r  = row + half * 8;
                float v0 = c[half * 2 + 0];
                float v1 = c[half * 2 + 1];
                size_t off = (size_t)r * Nd + col;
                if (EPI == 0) {
                    *(unsigned*)((__nv_bfloat16*)CoutV + off) = packbf(v0, v1);
                } else if (EPI == 2) {
                    v0 = gelu_exact(v0 + bias[col]);
                    v1 = gelu_exact(v1 + bias[col + 1]);
                    *(unsigned*)((__nv_bfloat16*)CoutV + off) = packbf(v0, v1);
                } else { // EPI == 3
                    v0 += bias[col]     + resid[off];
                    v1 += bias[col + 1] + resid[off + 1];
                    ((float2*)((float*)CoutV + off))[0] = make_float2(v0, v1);
                }
            }
        }
    }
}

// ---------------------------------------------------------------------------
// Tensor-core windowed attention + fused LePE.
// One CTA per (branch, window, head, half): 256 q x 512 k, hd=16, bf16 mma.
// ---------------------------------------------------------------------------
__global__ void __launch_bounds__(256, 3)
attn_mma_kernel(const __nv_bfloat16* __restrict__ qkv,
                const float* __restrict__ conv_w0, const float* __restrict__ conv_b0,
                const float* __restrict__ conv_w1, const float* __restrict__ conv_b1)
{
    __shared__ __nv_bfloat16 Ks[512 * 24];
    __shared__ __nv_bfloat16 Vt[16 * 520];
    __shared__ float cw[16 * 27];
    __shared__ float cb[16];

    int cta    = blockIdx.x;
    int branch = cta >> 9;
    int rem    = cta & 511;
    int win    = rem >> 3;
    int head   = (rem >> 1) & 3;
    int half   = rem & 1;

    int Hsp   = branch ? 4 : 32;
    int Wsp   = branch ? 32 : 4;
    int lw    = branch ? 5 : 2;
    int wmask = Wsp - 1;
    int nWw   = branch ? 1 : 8;

    int bidx = win >> 4;
    int wrem = win & 15;
    int wt   = wrem >> 3;
    int wsp  = wrem & 7;
    int wh   = wsp / nWw;
    int ww   = wsp % nWw;

    int choff = branch * 64 + head * 16;
    int tid  = threadIdx.x;
    int lane = tid & 31;
    int warp = tid >> 5;

    #define ROW_OF(p, itv, ihv, iwv, lrowv)                              \
        int itv = (p) >> 7;                                              \
        int ihv = ((p) & 127) >> lw;                                     \
        int iwv = (p) & wmask;                                           \
        int lrowv = bidx * LL + ((wt * 4 + itv) << 10)                   \
                  + ((wh * Hsp + ihv) << 5) + (ww * Wsp + iwv);

    // ---- stage K (row-major, pad 24) and V (transposed [16][520]) ----
    for (int p = tid; p < 512; p += 256) {
        ROW_OF(p, a_, b_, c_, lrow); (void)a_; (void)b_; (void)c_;
        const uint4* kp = (const uint4*)(qkv + (size_t)lrow * 384 + 128 + choff);
        uint4 k0 = kp[0], k1 = kp[1];
        *(uint4*)(Ks + p * 24 + 0) = k0;
        *(uint4*)(Ks + p * 24 + 8) = k1;
        const uint4* vp = (const uint4*)(qkv + (size_t)lrow * 384 + 256 + choff);
        uint4 v0 = vp[0], v1 = vp[1];
        __nv_bfloat16 vtmp[16];
        *(uint4*)(vtmp + 0) = v0;
        *(uint4*)(vtmp + 8) = v1;
        #pragma unroll
        for (int d = 0; d < 16; d++) Vt[d * 520 + p] = vtmp[d];
    }
    const float* cwp = branch ? conv_w1 : conv_w0;
    const float* cbp = branch ? conv_b1 : conv_b0;
    for (int i = tid; i < 16 * 27; i += 256) cw[i] = cwp[head * 432 + i];
    if (tid < 16) cb[tid] = cbp[head * 16 + tid];

    // ---- Q a-frags: scale = 0.25 * log2(e) so scores feed ex2 directly ----
    int qr = lane >> 2;
    int qc = (lane & 3) * 2;
    __nv_bfloat162 qscale = __float2bfloat162_rn(0.25f * 1.4426950408889634f);
    unsigned qa[2][4];
    int qbase = half * 256 + warp * 32;
    #pragma unroll
    for (int mt = 0; mt < 2; mt++) {
        int pr0 = qbase + mt * 16 + qr;
        int pr1 = pr0 + 8;
        ROW_OF(pr0, a0_, b0_, c0_, lrow0); (void)a0_; (void)b0_; (void)c0_;
        ROW_OF(pr1, a1_, b1_, c1_, lrow1); (void)a1_; (void)b1_; (void)c1_;
        const __nv_bfloat16* q0p = qkv + (size_t)lrow0 * 384 + choff;
        const __nv_bfloat16* q1p = qkv + (size_t)lrow1 * 384 + choff;
        __nv_bfloat162 t;
        t = __hmul2(*(const __nv_bfloat162*)(q0p + qc),     qscale); qa[mt][0] = __bf2u(t);
        t = __hmul2(*(const __nv_bfloat162*)(q1p + qc),     qscale); qa[mt][1] = __bf2u(t);
        t = __hmul2(*(const __nv_bfloat162*)(q0p + qc + 8), qscale); qa[mt][2] = __bf2u(t);
        t = __hmul2(*(const __nv_bfloat162*)(q1p + qc + 8), qscale); qa[mt][3] = __bf2u(t);
    }
    __syncthreads();

    // ---- streaming attention over 16 k-tiles of 32 keys ----
    float oAcc[2][2][4];
    float sAcc[2][4];
    #pragma unroll
    for (int mt = 0; mt < 2; mt++) {
        #pragma unroll
        for (int nf = 0; nf < 2; nf++)
            #pragma unroll
            for (int r = 0; r < 4; r++) oAcc[mt][nf][r] = 0.0f;
        #pragma unroll
        for (int r = 0; r < 4; r++) sAcc[mt][r] = 0.0f;
    }

    unsigned ones = (lane < 4) ? packbf(1.0f, 1.0f) : 0u;

    int g = lane >> 3;
    unsigned ksBase = (unsigned)__cvta_generic_to_shared(Ks);
    unsigned vtBase = (unsigned)__cvta_generic_to_shared(Vt);
    unsigned kRowOff = ((g & 1) * 8 + (lane & 7)) * 24 * 2 + (g >> 1) * 8 * 2;
    unsigned vRowOff = ((g & 1) * 8 + (lane & 7)) * 520 * 2 + (g >> 1) * 8 * 2;

    for (int kt = 0; kt < 16; kt++) {
        unsigned kb[4][2];
        {
            unsigned u0, u1, u2, u3;
            unsigned base = ksBase + kt * 32 * 24 * 2 + kRowOff;
            ldsm4(u0, u1, u2, u3, base);
            kb[0][0] = u0; kb[0][1] = u2; kb[1][0] = u1; kb[1][1] = u3;
            ldsm4(u0, u1, u2, u3, base + 16 * 24 * 2);
            kb[2][0] = u0; kb[2][1] = u2; kb[3][0] = u1; kb[3][1] = u3;
        }
        unsigned vb[4][2];
        {
            unsigned u0, u1, u2, u3;
            unsigned base = vtBase + kt * 32 * 2 + vRowOff;
            ldsm4(u0, u1, u2, u3, base);
            vb[0][0] = u0; vb[0][1] = u2; vb[1][0] = u1; vb[1][1] = u3;
            ldsm4(u0, u1, u2, u3, base + 16 * 2);
            vb[2][0] = u0; vb[2][1] = u2; vb[3][0] = u1; vb[3][1] = u3;
        }

        #pragma unroll
        for (int mt = 0; mt < 2; mt++) {
            float s[4][4];
            #pragma unroll
            for (int nf = 0; nf < 4; nf++) {
                s[nf][0] = 0.0f; s[nf][1] = 0.0f; s[nf][2] = 0.0f; s[nf][3] = 0.0f;
                mma16816(s[nf], qa[mt], kb[nf][0], kb[nf][1]);
            }
            #pragma unroll
            for (int nf = 0; nf < 4; nf++) {
                #pragma unroll
                for (int e = 0; e < 4; e++)
                    s[nf][e] = ex2f(fminf(s[nf][e], 43.0f));
            }
            unsigned pa0[4], pa1[4];
            pa0[0] = packbf(s[0][0], s[0][1]);
            pa0[1] = packbf(s[0][2], s[0][3]);
            pa0[2] = packbf(s[1][0], s[1][1]);
            pa0[3] = packbf(s[1][2], s[1][3]);
            pa1[0] = packbf(s[2][0], s[2][1]);
            pa1[1] = packbf(s[2][2], s[2][3]);
            pa1[2] = packbf(s[3][0], s[3][1]);
            pa1[3] = packbf(s[3][2], s[3][3]);
            mma16816(oAcc[mt][0], pa0, vb[0][0], vb[0][1]);
            mma16816(oAcc[mt][1], pa0, vb[1][0], vb[1][1]);
            mma16816(sAcc[mt],    pa0, ones,     ones);
            mma16816(oAcc[mt][0], pa1, vb[2][0], vb[2][1]);
            mma16816(oAcc[mt][1], pa1, vb[3][0], vb[3][1]);
            mma16816(sAcc[mt],    pa1, ones,     ones);
        }
    }

    float inv[2][2];
    #pragma unroll
    for (int mt = 0; mt < 2; mt++) {
        float s0 = __shfl_sync(0xffffffffu, sAcc[mt][0], lane & 28);
        float s1 = __shfl_sync(0xffffffffu, sAcc[mt][2], lane & 28);
        inv[mt][0] = 1.0f / s0;
        inv[mt][1] = 1.0f / s1;
    }

    #pragma unroll
    for (int mt = 0; mt < 2; mt++) {
        #pragma unroll
        for (int h = 0; h < 2; h++) {
            int p = qbase + mt * 16 + qr + h * 8;
            ROW_OF(p, it, ih, iw, lrow);
            float iv = inv[mt][h];
            int d0 = qc, d2 = qc + 8;
            float a0 = oAcc[mt][0][h * 2 + 0] * iv + cb[d0];
            float a1 = oAcc[mt][0][h * 2 + 1] * iv + cb[d0 + 1];
            float a2 = oAcc[mt][1][h * 2 + 0] * iv + cb[d2];
            float a3 = oAcc[mt][1][h * 2 + 1] * iv + cb[d2 + 1];

            #pragma unroll
            for (int dz = 0; dz < 3; dz++) {
                int z = it + dz - 1;
                if (z < 0 || z >= 4) continue;
                #pragma unroll
                for (int dy = 0; dy < 3; dy++) {
                    int y = ih + dy - 1;
                    if (y < 0 || y >= Hsp) continue;
                    #pragma unroll
                    for (int dx = 0; dx < 3; dx++) {
                        int x = iw + dx - 1;
                        if (x < 0 || x >= Wsp) continue;
                        int widx = dz * 9 + dy * 3 + dx;
                        int pos = (z << 7) + (y << lw) + x;
                        a0 += cw[d0 * 27 + widx]       * __bfloat162float(Vt[d0 * 520 + pos]);
                        a1 += cw[(d0 + 1) * 27 + widx] * __bfloat162float(Vt[(d0 + 1) * 520 + pos]);
                        a2 += cw[d2 * 27 + widx]       * __bfloat162float(Vt[d2 * 520 + pos]);
                        a3 += cw[(d2 + 1) * 27 + widx] * __bfloat162float(Vt[(d2 + 1) * 520 + pos]);
                    }
                }
            }
            __nv_bfloat16* op = g_att + (size_t)lrow * CC + choff;
            *(unsigned*)(op + d0) = packbf(a0, a1);
            *(unsigned*)(op + d2) = packbf(a2, a3);
        }
    }
    #undef ROW_OF
}

// ---------------------------------------------------------------------------
// Launch
// ---------------------------------------------------------------------------
extern "C" void kernel_launch(void* const* d_in, const int* in_sizes, int n_in,
                              void* d_out, int out_size)
{
    const float* x       = (const float*)d_in[0];
    const float* norm1_w = (const float*)d_in[1];
    const float* norm1_b = (const float*)d_in[2];
    const float* qkv_w   = (const float*)d_in[3];
    const float* conv_w0 = (const float*)d_in[4];
    const float* conv_b0 = (const float*)d_in[5];
    const float* conv_w1 = (const float*)d_in[6];
    const float* conv_b1 = (const float*)d_in[7];
    const float* proj_w  = (const float*)d_in[8];
    const float* proj_b  = (const float*)d_in[9];
    const float* norm2_w = (const float*)d_in[10];
    const float* norm2_b = (const float*)d_in[11];
    const float* fc1_w   = (const float*)d_in[12];
    const float* fc1_b   = (const float*)d_in[13];
    const float* fc2_w   = (const float*)d_in[14];
    const float* fc2_b   = (const float*)d_in[15];
    float* out = (float*)d_out;

    __nv_bfloat16 *p_img, *p_att, *p_y, *p_hid, *p_qkv;
    __nv_bfloat16 *p_wqkv, *p_wproj, *p_wfc1, *p_wfc2;
    float *p_x2;
    cudaGetSymbolAddress((void**)&p_img, g_img);
    cudaGetSymbolAddress((void**)&p_qkv, g_qkv);
    cudaGetSymbolAddress((void**)&p_att, g_att);
    cudaGetSymbolAddress((void**)&p_x2,  g_x2);
    cudaGetSymbolAddress((void**)&p_y,   g_y);
    cudaGetSymbolAddress((void**)&p_hid, g_hid);
    cudaGetSymbolAddress((void**)&p_wqkv,  g_wqkv);
    cudaGetSymbolAddress((void**)&p_wproj, g_wproj);
    cudaGetSymbolAddress((void**)&p_wfc1,  g_wfc1);
    cudaGetSymbolAddress((void**)&p_wfc2,  g_wfc2);

    dim3 lnBlock(32, 8);

    // 0. weights -> bf16
    convert_weights<<<768, 256>>>(qkv_w, proj_w, fc1_w, fc2_w);

    // 1. LN1 -> bf16
    ln_kernel<<<MROWS / 8, lnBlock>>>(x, norm1_w, norm1_b, p_img);

    // 2. QKV GEMM -> bf16
    hgemm_kernel<0><<<dim3(3, MROWS / 128), 256>>>(
        384, 128, p_img, p_wqkv, nullptr, nullptr, p_qkv,
        nullptr, nullptr, nullptr);

    // 3. Tensor-core attention + LePE -> bf16
    attn_mma_kernel<<<1024, 256>>>(p_qkv, conv_w0, conv_b0, conv_w1, conv_b1);

    // 4. proj + bias + residual(x) -> x2 (fp32)  +  fused LN2 -> y (bf16)
    hgemm_kernel<4><<<dim3(1, MROWS / 128), 256>>>(
        128, 128, p_att, p_wproj, proj_b, x, p_x2,
        norm2_w, norm2_b, p_y);

    // 5. fc1 + bias + gelu -> bf16
    hgemm_kernel<2><<<dim3(4, MROWS / 128), 256>>>(
        512, 128, p_y, p_wfc1, fc1_b, nullptr, p_hid,
        nullptr, nullptr, nullptr);

    // 6. fc2 + bias + residual(x2) -> out (fp32)
    hgemm_kernel<3><<<dim3(1, MROWS / 128), 256>>>(
        128, 512, p_hid, p_wfc2, fc2_b, p_x2, out,
        nullptr, nullptr, nullptr);
}